// round 1
// baseline (speedup 1.0000x reference)
#include <cuda_runtime.h>
#include <math.h>

#define NB      2
#define SEQ     2048
#define DMODEL  512
#define VOCAB   32000
#define NHEADS  8
#define DHEAD   64
#define DFFN    2048
#define NDEPTH  6
#define MROWS   (NB*SEQ)   /* 4096 */

#define RES_SCALE 1.86120971820393f   /* (2*6)^0.25 */
#define ATTN_SCALE 8.0f
#define LN_EPS 1e-5f

/* ---------------- scratch (no cudaMalloc allowed) ---------------- */
__device__ float g_h [MROWS*DMODEL];
__device__ float g_q [MROWS*DMODEL];
__device__ float g_k [MROWS*DMODEL];
__device__ float g_v [MROWS*DMODEL];
__device__ float g_a [MROWS*DMODEL];
__device__ float g_t [MROWS*DMODEL];
__device__ float g_ff[MROWS*DFFN];

/* ---------------- embedding ---------------- */
__global__ void embed_kernel(const int* __restrict__ x, const float* __restrict__ tok,
                             const float* __restrict__ pos, float* __restrict__ h) {
    int idx = blockIdx.x * 256 + threadIdx.x;      // over MROWS*DMODEL
    int row = idx >> 9;
    int d   = idx & 511;
    int n   = row & (SEQ - 1);
    h[idx] = tok[x[row] * DMODEL + d] + pos[n * DMODEL + d];
}

/* ---------------- tiled fp32 GEMM: C = A[MxK] * B[KxN], row-major ----------------
   BM=BN=64, BK=16, 256 threads, 4x4 per thread. EPI: 0=none, 1=exact GELU. */
template<int EPI>
__global__ void gemm_kernel(const float* __restrict__ A, const float* __restrict__ B,
                            float* __restrict__ C, int M, int N, int K) {
    __shared__ float As[16][64];      // transposed: As[k][m]
    __shared__ float Bs[16][64];      // Bs[k][n]
    int tid = threadIdx.x;
    int tx = tid & 15, ty = tid >> 4;
    int bm = blockIdx.y * 64, bn = blockIdx.x * 64;

    float acc[4][4] = {};
    int a_m = tid >> 2;            // 0..63
    int a_k = (tid & 3) * 4;       // 0,4,8,12
    int b_k = tid >> 4;            // 0..15
    int b_n = (tid & 15) * 4;

    const float* Aptr = A + (size_t)(bm + a_m) * K + a_k;
    const float* Bptr = B + (size_t)b_k * N + bn + b_n;

    for (int k0 = 0; k0 < K; k0 += 16) {
        float4 av = *(const float4*)Aptr;  Aptr += 16;
        As[a_k + 0][a_m] = av.x;
        As[a_k + 1][a_m] = av.y;
        As[a_k + 2][a_m] = av.z;
        As[a_k + 3][a_m] = av.w;
        float4 bv = *(const float4*)Bptr;  Bptr += (size_t)16 * N;
        *(float4*)&Bs[b_k][b_n] = bv;
        __syncthreads();
#pragma unroll
        for (int d = 0; d < 16; d++) {
            float4 a4 = *(const float4*)&As[d][ty * 4];
            float4 b4 = *(const float4*)&Bs[d][tx * 4];
            float ar[4] = {a4.x, a4.y, a4.z, a4.w};
            float br[4] = {b4.x, b4.y, b4.z, b4.w};
#pragma unroll
            for (int i = 0; i < 4; i++)
#pragma unroll
                for (int j = 0; j < 4; j++)
                    acc[i][j] = fmaf(ar[i], br[j], acc[i][j]);
        }
        __syncthreads();
    }
#pragma unroll
    for (int i = 0; i < 4; i++) {
        float4 o;
        float* op = (float*)&o;
#pragma unroll
        for (int j = 0; j < 4; j++) {
            float vv = acc[i][j];
            if (EPI == 1) vv = 0.5f * vv * (1.0f + erff(vv * 0.70710678118654752f));
            op[j] = vv;
        }
        *(float4*)&C[(size_t)(bm + ty * 4 + i) * N + bn + tx * 4] = o;
    }
}

/* ---------------- per-head L2 normalize of q,k (64-vectors, contiguous) ------- */
__global__ void l2norm_kernel(float* __restrict__ q, float* __restrict__ k) {
    int w    = (blockIdx.x * blockDim.x + threadIdx.x) >> 5;
    int lane = threadIdx.x & 31;
    float* base = (w < MROWS * NHEADS) ? (q + (size_t)w * 64)
                                       : (k + (size_t)(w - MROWS * NHEADS) * 64);
    float a = base[lane], c = base[lane + 32];
    float ss = a * a + c * c;
#pragma unroll
    for (int o = 16; o; o >>= 1) ss += __shfl_xor_sync(0xffffffffu, ss, o);
    float inv = 1.0f / fmaxf(sqrtf(ss), 1e-12f);
    base[lane]      = a * inv;
    base[lane + 32] = c * inv;
}

/* ---------------- flash attention, fp32, 64q x 64k tiles ---------------- */
__global__ void attn_kernel(const float* __restrict__ q, const float* __restrict__ k,
                            const float* __restrict__ v, float* __restrict__ o) {
    extern __shared__ float sm[];
    float* Qt  = sm;                 // [64][68] transposed (d-major)
    float* Kt  = Qt + 64 * 68;       // [64][68] transposed
    float* Vs  = Kt + 64 * 68;       // [64][68] row-major
    float* St  = Vs + 64 * 68;       // [64][68] scores^T: St[j][i]
    float* m_s = St + 64 * 68;
    float* l_s = m_s + 64;
    float* c_s = l_s + 64;

    int qt = blockIdx.x, hh = blockIdx.y, b = blockIdx.z;
    int tid = threadIdx.x, tx = tid & 15, ty = tid >> 4;

    for (int i = tid; i < 4096; i += 256) {
        int r = i >> 6, c = i & 63;
        Qt[c * 68 + r] = q[(size_t)(b * SEQ + qt * 64 + r) * DMODEL + hh * 64 + c];
    }
    if (tid < 64) { m_s[tid] = -1e30f; l_s[tid] = 0.0f; }
    float acc[4][4] = {};
    __syncthreads();

    for (int kt = 0; kt <= qt; kt++) {
        for (int i = tid; i < 4096; i += 256) {
            int r = i >> 6, c = i & 63;
            size_t g = (size_t)(b * SEQ + kt * 64 + r) * DMODEL + hh * 64 + c;
            Kt[c * 68 + r] = k[g];
            Vs[r * 68 + c] = v[g];
        }
        __syncthreads();

        float s[4][4] = {};
#pragma unroll 4
        for (int d = 0; d < 64; d++) {
            float4 qa = *(const float4*)&Qt[d * 68 + ty * 4];
            float4 kb = *(const float4*)&Kt[d * 68 + tx * 4];
            float qr[4] = {qa.x, qa.y, qa.z, qa.w};
            float kr[4] = {kb.x, kb.y, kb.z, kb.w};
#pragma unroll
            for (int i = 0; i < 4; i++)
#pragma unroll
                for (int j = 0; j < 4; j++)
                    s[i][j] = fmaf(qr[i], kr[j], s[i][j]);
        }
        int qg0 = qt * 64 + ty * 4, kg0 = kt * 64 + tx * 4;
#pragma unroll
        for (int i = 0; i < 4; i++)
#pragma unroll
            for (int j = 0; j < 4; j++) {
                float val = s[i][j] * ATTN_SCALE;
                if (kg0 + j > qg0 + i) val = -1e30f;
                St[(tx * 4 + j) * 68 + ty * 4 + i] = val;
            }
        __syncthreads();

        if (tid < 64) {
            int r = tid;
            float mo = m_s[r];
            float mx = -1e30f;
            for (int j = 0; j < 64; j++) mx = fmaxf(mx, St[j * 68 + r]);
            float mn = fmaxf(mo, mx);
            float corr = __expf(mo - mn);
            float sum = 0.0f;
            for (int j = 0; j < 64; j++) {
                float p = __expf(St[j * 68 + r] - mn);
                St[j * 68 + r] = p;
                sum += p;
            }
            m_s[r] = mn;
            l_s[r] = l_s[r] * corr + sum;
            c_s[r] = corr;
        }
        __syncthreads();

        float cr[4];
#pragma unroll
        for (int i = 0; i < 4; i++) cr[i] = c_s[ty * 4 + i];
#pragma unroll
        for (int i = 0; i < 4; i++)
#pragma unroll
            for (int j = 0; j < 4; j++) acc[i][j] *= cr[i];

#pragma unroll 4
        for (int j = 0; j < 64; j++) {
            float4 pa = *(const float4*)&St[j * 68 + ty * 4];
            float4 vv = *(const float4*)&Vs[j * 68 + tx * 4];
            float pr[4] = {pa.x, pa.y, pa.z, pa.w};
            float vr[4] = {vv.x, vv.y, vv.z, vv.w};
#pragma unroll
            for (int i = 0; i < 4; i++)
#pragma unroll
                for (int jj = 0; jj < 4; jj++)
                    acc[i][jj] = fmaf(pr[i], vr[jj], acc[i][jj]);
        }
        __syncthreads();
    }

#pragma unroll
    for (int i = 0; i < 4; i++) {
        float inv = 1.0f / l_s[ty * 4 + i];
#pragma unroll
        for (int j = 0; j < 4; j++)
            o[(size_t)(b * SEQ + qt * 64 + ty * 4 + i) * DMODEL + hh * 64 + tx * 4 + j]
                = acc[i][j] * inv;
    }
}

/* ---------------- fused residual + LayerNorm (in-place on h) ---------------- */
__global__ void ln_res_kernel(float* __restrict__ h, const float* __restrict__ a,
                              const float* __restrict__ g, const float* __restrict__ bb) {
    __shared__ float red[8];
    __shared__ float s_stat[2];
    int row = blockIdx.x, tid = threadIdx.x;
    size_t base = (size_t)row * DMODEL;
    float x0 = fmaf(RES_SCALE, h[base + tid],       a[base + tid]);
    float x1 = fmaf(RES_SCALE, h[base + tid + 256], a[base + tid + 256]);

    float s = x0 + x1;
#pragma unroll
    for (int o = 16; o; o >>= 1) s += __shfl_xor_sync(0xffffffffu, s, o);
    if ((tid & 31) == 0) red[tid >> 5] = s;
    __syncthreads();
    if (tid < 8) {
        s = red[tid];
#pragma unroll
        for (int o = 4; o; o >>= 1) s += __shfl_xor_sync(0xffu, s, o);
        if (tid == 0) s_stat[0] = s * (1.0f / DMODEL);
    }
    __syncthreads();
    float mean = s_stat[0];
    float d0 = x0 - mean, d1 = x1 - mean;
    float vv = d0 * d0 + d1 * d1;
#pragma unroll
    for (int o = 16; o; o >>= 1) vv += __shfl_xor_sync(0xffffffffu, vv, o);
    if ((tid & 31) == 0) red[tid >> 5] = vv;
    __syncthreads();
    if (tid < 8) {
        vv = red[tid];
#pragma unroll
        for (int o = 4; o; o >>= 1) vv += __shfl_xor_sync(0xffu, vv, o);
        if (tid == 0) s_stat[1] = rsqrtf(vv * (1.0f / DMODEL) + LN_EPS);
    }
    __syncthreads();
    float inv = s_stat[1];
    h[base + tid]       = d0 * inv * g[tid]       + bb[tid];
    h[base + tid + 256] = d1 * inv * g[tid + 256] + bb[tid + 256];
}

/* ---------------- host driver ---------------- */
#define ATTN_SMEM ((4 * 64 * 68 + 3 * 64) * 4)

extern "C" void kernel_launch(void* const* d_in, const int* in_sizes, int n_in,
                              void* d_out, int out_size) {
    const int*   x    = (const int*)  d_in[0];
    const float* tok  = (const float*)d_in[1];
    const float* pos  = (const float*)d_in[2];
    const float* Wq   = (const float*)d_in[3];
    const float* Wk   = (const float*)d_in[4];
    const float* Wv   = (const float*)d_in[5];
    const float* Wo   = (const float*)d_in[6];
    const float* ln1g = (const float*)d_in[7];
    const float* ln1b = (const float*)d_in[8];
    const float* W1   = (const float*)d_in[9];
    const float* W2   = (const float*)d_in[10];
    const float* ln2g = (const float*)d_in[11];
    const float* ln2b = (const float*)d_in[12];
    const float* Wl   = (const float*)d_in[13];
    float* out = (float*)d_out;

    float *ph, *pq, *pk, *pv, *pa, *pt, *pff;
    cudaGetSymbolAddress((void**)&ph,  g_h);
    cudaGetSymbolAddress((void**)&pq,  g_q);
    cudaGetSymbolAddress((void**)&pk,  g_k);
    cudaGetSymbolAddress((void**)&pv,  g_v);
    cudaGetSymbolAddress((void**)&pa,  g_a);
    cudaGetSymbolAddress((void**)&pt,  g_t);
    cudaGetSymbolAddress((void**)&pff, g_ff);

    cudaFuncSetAttribute(attn_kernel, cudaFuncAttributeMaxDynamicSharedMemorySize, ATTN_SMEM);

    embed_kernel<<<MROWS * DMODEL / 256, 256>>>(x, tok, pos, ph);

    for (int i = 0; i < NDEPTH; i++) {
        const float* wq = Wq + (size_t)i * DMODEL * DMODEL;
        const float* wk = Wk + (size_t)i * DMODEL * DMODEL;
        const float* wv = Wv + (size_t)i * DMODEL * DMODEL;
        const float* wo = Wo + (size_t)i * DMODEL * DMODEL;
        const float* w1 = W1 + (size_t)i * DMODEL * DFFN;
        const float* w2 = W2 + (size_t)i * DFFN * DMODEL;

        dim3 gS(DMODEL / 64, MROWS / 64);
        gemm_kernel<0><<<gS, 256>>>(ph, wq, pq, MROWS, DMODEL, DMODEL);
        gemm_kernel<0><<<gS, 256>>>(ph, wk, pk, MROWS, DMODEL, DMODEL);
        gemm_kernel<0><<<gS, 256>>>(ph, wv, pv, MROWS, DMODEL, DMODEL);

        l2norm_kernel<<<(2 * MROWS * NHEADS) / 8, 256>>>(pq, pk);

        attn_kernel<<<dim3(SEQ / 64, NHEADS, NB), 256, ATTN_SMEM>>>(pq, pk, pv, pa);

        gemm_kernel<0><<<gS, 256>>>(pa, wo, pt, MROWS, DMODEL, DMODEL);
        ln_res_kernel<<<MROWS, 256>>>(ph, pt, ln1g + i * DMODEL, ln1b + i * DMODEL);

        gemm_kernel<1><<<dim3(DFFN / 64, MROWS / 64), 256>>>(ph, w1, pff, MROWS, DFFN, DMODEL);
        gemm_kernel<0><<<gS, 256>>>(pff, w2, pt, MROWS, DMODEL, DFFN);
        ln_res_kernel<<<MROWS, 256>>>(ph, pt, ln2g + i * DMODEL, ln2b + i * DMODEL);
    }

    gemm_kernel<0><<<dim3(VOCAB / 64, MROWS / 64), 256>>>(ph, Wl, out, MROWS, VOCAB, DMODEL);
}

// round 2
// speedup vs baseline: 2.1451x; 2.1451x over previous
#include <cuda_runtime.h>
#include <math.h>

#define NB      2
#define SEQ     2048
#define DMODEL  512
#define VOCAB   32000
#define NHEADS  8
#define DHEAD   64
#define DFFN    2048
#define NDEPTH  6
#define MROWS   (NB*SEQ)   /* 4096 */

#define RES_SCALE 1.86120971820393f   /* (2*6)^0.25 */
#define ATTN_SCALE 8.0f
#define LN_EPS 1e-5f

/* ---------------- scratch (no cudaMalloc allowed) ---------------- */
__device__ float g_h [MROWS*DMODEL];
__device__ float g_q [MROWS*DMODEL];
__device__ float g_k [MROWS*DMODEL];
__device__ float g_v [MROWS*DMODEL];
__device__ float g_a [MROWS*DMODEL];
__device__ float g_t [MROWS*DMODEL];
__device__ float g_ff[MROWS*DFFN];

/* ---------------- embedding ---------------- */
__global__ void embed_kernel(const int* __restrict__ x, const float* __restrict__ tok,
                             const float* __restrict__ pos, float* __restrict__ h) {
    int idx = blockIdx.x * 256 + threadIdx.x;
    int row = idx >> 9;
    int d   = idx & 511;
    int n   = row & (SEQ - 1);
    h[idx] = tok[x[row] * DMODEL + d] + pos[n * DMODEL + d];
}

/* ================= TF32 tensor-core GEMM =================
   C[M x N] = A[M x K] * B[K x N], row-major, all dims %128/%16 == 0.
   BM=BN=128, BK=16, 256 threads = 8 warps in 4x2, warp tile 32x64.
   mma.sync.m16n8k8 tf32. Double-buffered smem, cvt.rna at fill. */

#define SMB   (16*136)            /* one K-slab (padded) */
#define GEMM_SMEM (4*SMB*4)       /* 2 bufs x (As+Bs) x 4B = 34816 */

__device__ __forceinline__ float tf32r(float x) {
    unsigned u;
    asm("cvt.rna.tf32.f32 %0, %1;" : "=r"(u) : "f"(x));
    return __uint_as_float(u);
}

__device__ __forceinline__ void mma_tf32(float* d, const unsigned* a, unsigned b0, unsigned b1) {
    asm volatile(
        "mma.sync.aligned.m16n8k8.row.col.f32.tf32.tf32.f32 "
        "{%0,%1,%2,%3},{%4,%5,%6,%7},{%8,%9},{%0,%1,%2,%3};"
        : "+f"(d[0]), "+f"(d[1]), "+f"(d[2]), "+f"(d[3])
        : "r"(a[0]), "r"(a[1]), "r"(a[2]), "r"(a[3]), "r"(b0), "r"(b1));
}

template<int EPI>
__device__ __forceinline__ void gemm_body(const float* __restrict__ A,
                                          const float* __restrict__ B,
                                          float* __restrict__ C,
                                          int N, int K, float* sm) {
    float* As = sm;            /* [2][16][136], As[k][m] (transposed) */
    float* Bs = sm + 2 * SMB;  /* [2][16][136], Bs[k][n] */

    int tid  = threadIdx.x;
    int warp = tid >> 5, lane = tid & 31;
    int wm = warp >> 1, wn = warp & 1;     /* 4 x 2 warps */
    int g  = lane >> 2, tg = lane & 3;
    int bm = blockIdx.y * 128, bn = blockIdx.x * 128;

    int ar = tid >> 2;          /* A stage: row 0..63 (and +64), col (tid&3)*4 */
    int ac = (tid & 3) * 4;
    int br = tid >> 5;          /* B stage: row 0..7 (and +8), col (tid&31)*4 */
    int bc = (tid & 31) * 4;

    const float* Ap = A + (size_t)(bm + ar) * K + ac;
    const float* Bp = B + (size_t)br * N + bn + bc;

    float acc[2][8][4];
#pragma unroll
    for (int i = 0; i < 2; i++)
#pragma unroll
        for (int j = 0; j < 8; j++)
#pragma unroll
            for (int t = 0; t < 4; t++) acc[i][j][t] = 0.0f;

    float4 ra0, ra1, rb0, rb1;
    /* prefetch k-slab 0 */
    ra0 = *(const float4*)(Ap);
    ra1 = *(const float4*)(Ap + (size_t)64 * K);
    rb0 = *(const float4*)(Bp);
    rb1 = *(const float4*)(Bp + (size_t)8 * N);

    int nIter = K >> 4;
    int buf = 0;

    /* store slab 0 */
    {
        float* a0 = As + 0 * SMB;
        a0[(ac + 0) * 136 + ar]      = tf32r(ra0.x);
        a0[(ac + 1) * 136 + ar]      = tf32r(ra0.y);
        a0[(ac + 2) * 136 + ar]      = tf32r(ra0.z);
        a0[(ac + 3) * 136 + ar]      = tf32r(ra0.w);
        a0[(ac + 0) * 136 + ar + 64] = tf32r(ra1.x);
        a0[(ac + 1) * 136 + ar + 64] = tf32r(ra1.y);
        a0[(ac + 2) * 136 + ar + 64] = tf32r(ra1.z);
        a0[(ac + 3) * 136 + ar + 64] = tf32r(ra1.w);
        float4 c0 = make_float4(tf32r(rb0.x), tf32r(rb0.y), tf32r(rb0.z), tf32r(rb0.w));
        float4 c1 = make_float4(tf32r(rb1.x), tf32r(rb1.y), tf32r(rb1.z), tf32r(rb1.w));
        *(float4*)&Bs[0 * SMB + br * 136 + bc]       = c0;
        *(float4*)&Bs[0 * SMB + (br + 8) * 136 + bc] = c1;
    }
    __syncthreads();

    for (int it = 0; it < nIter; it++) {
        if (it + 1 < nIter) {
            int k0 = (it + 1) * 16;
            ra0 = *(const float4*)(Ap + k0);
            ra1 = *(const float4*)(Ap + (size_t)64 * K + k0);
            rb0 = *(const float4*)(Bp + (size_t)k0 * N);
            rb1 = *(const float4*)(Bp + (size_t)(k0 + 8) * N);
        }

        const float* a_s = As + buf * SMB;
        const float* b_s = Bs + buf * SMB;
#pragma unroll
        for (int ks = 0; ks < 2; ks++) {
            int k0 = ks * 8;
            unsigned af[2][4];
#pragma unroll
            for (int i = 0; i < 2; i++) {
                int mr = wm * 32 + i * 16 + g;
                af[i][0] = __float_as_uint(a_s[(k0 + tg)     * 136 + mr]);
                af[i][1] = __float_as_uint(a_s[(k0 + tg)     * 136 + mr + 8]);
                af[i][2] = __float_as_uint(a_s[(k0 + tg + 4) * 136 + mr]);
                af[i][3] = __float_as_uint(a_s[(k0 + tg + 4) * 136 + mr + 8]);
            }
#pragma unroll
            for (int j = 0; j < 8; j++) {
                int nc = wn * 64 + j * 8 + g;
                unsigned b0 = __float_as_uint(b_s[(k0 + tg)     * 136 + nc]);
                unsigned b1 = __float_as_uint(b_s[(k0 + tg + 4) * 136 + nc]);
                mma_tf32(acc[0][j], af[0], b0, b1);
                mma_tf32(acc[1][j], af[1], b0, b1);
            }
        }

        if (it + 1 < nIter) {
            float* a_d = As + (buf ^ 1) * SMB;
            a_d[(ac + 0) * 136 + ar]      = tf32r(ra0.x);
            a_d[(ac + 1) * 136 + ar]      = tf32r(ra0.y);
            a_d[(ac + 2) * 136 + ar]      = tf32r(ra0.z);
            a_d[(ac + 3) * 136 + ar]      = tf32r(ra0.w);
            a_d[(ac + 0) * 136 + ar + 64] = tf32r(ra1.x);
            a_d[(ac + 1) * 136 + ar + 64] = tf32r(ra1.y);
            a_d[(ac + 2) * 136 + ar + 64] = tf32r(ra1.z);
            a_d[(ac + 3) * 136 + ar + 64] = tf32r(ra1.w);
            float4 c0 = make_float4(tf32r(rb0.x), tf32r(rb0.y), tf32r(rb0.z), tf32r(rb0.w));
            float4 c1 = make_float4(tf32r(rb1.x), tf32r(rb1.y), tf32r(rb1.z), tf32r(rb1.w));
            *(float4*)&Bs[(buf ^ 1) * SMB + br * 136 + bc]       = c0;
            *(float4*)&Bs[(buf ^ 1) * SMB + (br + 8) * 136 + bc] = c1;
        }
        __syncthreads();
        buf ^= 1;
    }

    /* epilogue */
#pragma unroll
    for (int i = 0; i < 2; i++) {
        int r0 = bm + wm * 32 + i * 16 + g;
#pragma unroll
        for (int j = 0; j < 8; j++) {
            int col = bn + wn * 64 + j * 8 + tg * 2;
            float v0 = acc[i][j][0], v1 = acc[i][j][1];
            float v2 = acc[i][j][2], v3 = acc[i][j][3];
            if (EPI == 1) {
                v0 = 0.5f * v0 * (1.0f + erff(v0 * 0.70710678118654752f));
                v1 = 0.5f * v1 * (1.0f + erff(v1 * 0.70710678118654752f));
                v2 = 0.5f * v2 * (1.0f + erff(v2 * 0.70710678118654752f));
                v3 = 0.5f * v3 * (1.0f + erff(v3 * 0.70710678118654752f));
            }
            *(float2*)&C[(size_t)r0 * N + col]       = make_float2(v0, v1);
            *(float2*)&C[(size_t)(r0 + 8) * N + col] = make_float2(v2, v3);
        }
    }
}

template<int EPI>
__global__ __launch_bounds__(256) void gemm_tc(const float* __restrict__ A,
                                               const float* __restrict__ B,
                                               float* __restrict__ C, int N, int K) {
    extern __shared__ float sm[];
    gemm_body<EPI>(A, B, C, N, K, sm);
}

/* QKV fused: z picks which of the three projections this CTA computes */
__global__ __launch_bounds__(256) void gemm_qkv(const float* __restrict__ A,
                                                const float* __restrict__ B0,
                                                const float* __restrict__ B1,
                                                const float* __restrict__ B2,
                                                float* __restrict__ C0,
                                                float* __restrict__ C1,
                                                float* __restrict__ C2,
                                                int N, int K) {
    extern __shared__ float sm[];
    const float* B = (blockIdx.z == 0) ? B0 : (blockIdx.z == 1) ? B1 : B2;
    float*       C = (blockIdx.z == 0) ? C0 : (blockIdx.z == 1) ? C1 : C2;
    gemm_body<0>(A, B, C, N, K, sm);
}

/* ---------------- per-head L2 normalize of q,k ---------------- */
__global__ void l2norm_kernel(float* __restrict__ q, float* __restrict__ k) {
    int w    = (blockIdx.x * blockDim.x + threadIdx.x) >> 5;
    int lane = threadIdx.x & 31;
    float* base = (w < MROWS * NHEADS) ? (q + (size_t)w * 64)
                                       : (k + (size_t)(w - MROWS * NHEADS) * 64);
    float a = base[lane], c = base[lane + 32];
    float ss = a * a + c * c;
#pragma unroll
    for (int o = 16; o; o >>= 1) ss += __shfl_xor_sync(0xffffffffu, ss, o);
    float inv = 1.0f / fmaxf(sqrtf(ss), 1e-12f);
    base[lane]      = a * inv;
    base[lane + 32] = c * inv;
}

/* ---------------- flash attention, fp32, 64q x 64k tiles ---------------- */
__global__ void attn_kernel(const float* __restrict__ q, const float* __restrict__ k,
                            const float* __restrict__ v, float* __restrict__ o) {
    extern __shared__ float sm[];
    float* Qt  = sm;
    float* Kt  = Qt + 64 * 68;
    float* Vs  = Kt + 64 * 68;
    float* St  = Vs + 64 * 68;
    float* m_s = St + 64 * 68;
    float* l_s = m_s + 64;
    float* c_s = l_s + 64;

    int qt = blockIdx.x, hh = blockIdx.y, b = blockIdx.z;
    int tid = threadIdx.x, tx = tid & 15, ty = tid >> 4;

    for (int i = tid; i < 4096; i += 256) {
        int r = i >> 6, c = i & 63;
        Qt[c * 68 + r] = q[(size_t)(b * SEQ + qt * 64 + r) * DMODEL + hh * 64 + c];
    }
    if (tid < 64) { m_s[tid] = -1e30f; l_s[tid] = 0.0f; }
    float acc[4][4] = {};
    __syncthreads();

    for (int kt = 0; kt <= qt; kt++) {
        for (int i = tid; i < 4096; i += 256) {
            int r = i >> 6, c = i & 63;
            size_t gg = (size_t)(b * SEQ + kt * 64 + r) * DMODEL + hh * 64 + c;
            Kt[c * 68 + r] = k[gg];
            Vs[r * 68 + c] = v[gg];
        }
        __syncthreads();

        float s[4][4] = {};
#pragma unroll 4
        for (int d = 0; d < 64; d++) {
            float4 qa = *(const float4*)&Qt[d * 68 + ty * 4];
            float4 kb = *(const float4*)&Kt[d * 68 + tx * 4];
            float qr[4] = {qa.x, qa.y, qa.z, qa.w};
            float kr[4] = {kb.x, kb.y, kb.z, kb.w};
#pragma unroll
            for (int i = 0; i < 4; i++)
#pragma unroll
                for (int j = 0; j < 4; j++)
                    s[i][j] = fmaf(qr[i], kr[j], s[i][j]);
        }
        int qg0 = qt * 64 + ty * 4, kg0 = kt * 64 + tx * 4;
#pragma unroll
        for (int i = 0; i < 4; i++)
#pragma unroll
            for (int j = 0; j < 4; j++) {
                float val = s[i][j] * ATTN_SCALE;
                if (kg0 + j > qg0 + i) val = -1e30f;
                St[(tx * 4 + j) * 68 + ty * 4 + i] = val;
            }
        __syncthreads();

        if (tid < 64) {
            int r = tid;
            float mo = m_s[r];
            float mx = -1e30f;
            for (int j = 0; j < 64; j++) mx = fmaxf(mx, St[j * 68 + r]);
            float mn = fmaxf(mo, mx);
            float corr = __expf(mo - mn);
            float sum = 0.0f;
            for (int j = 0; j < 64; j++) {
                float p = __expf(St[j * 68 + r] - mn);
                St[j * 68 + r] = p;
                sum += p;
            }
            m_s[r] = mn;
            l_s[r] = l_s[r] * corr + sum;
            c_s[r] = corr;
        }
        __syncthreads();

        float cr[4];
#pragma unroll
        for (int i = 0; i < 4; i++) cr[i] = c_s[ty * 4 + i];
#pragma unroll
        for (int i = 0; i < 4; i++)
#pragma unroll
            for (int j = 0; j < 4; j++) acc[i][j] *= cr[i];

#pragma unroll 4
        for (int j = 0; j < 64; j++) {
            float4 pa = *(const float4*)&St[j * 68 + ty * 4];
            float4 vv = *(const float4*)&Vs[j * 68 + tx * 4];
            float pr[4] = {pa.x, pa.y, pa.z, pa.w};
            float vr[4] = {vv.x, vv.y, vv.z, vv.w};
#pragma unroll
            for (int i = 0; i < 4; i++)
#pragma unroll
                for (int jj = 0; jj < 4; jj++)
                    acc[i][jj] = fmaf(pr[i], vr[jj], acc[i][jj]);
        }
        __syncthreads();
    }

#pragma unroll
    for (int i = 0; i < 4; i++) {
        float inv = 1.0f / l_s[ty * 4 + i];
#pragma unroll
        for (int j = 0; j < 4; j++)
            o[(size_t)(b * SEQ + qt * 64 + ty * 4 + i) * DMODEL + hh * 64 + tx * 4 + j]
                = acc[i][j] * inv;
    }
}

/* ---------------- fused residual + LayerNorm ---------------- */
__global__ void ln_res_kernel(float* __restrict__ h, const float* __restrict__ a,
                              const float* __restrict__ g, const float* __restrict__ bb) {
    __shared__ float red[8];
    __shared__ float s_stat[2];
    int row = blockIdx.x, tid = threadIdx.x;
    size_t base = (size_t)row * DMODEL;
    float x0 = fmaf(RES_SCALE, h[base + tid],       a[base + tid]);
    float x1 = fmaf(RES_SCALE, h[base + tid + 256], a[base + tid + 256]);

    float s = x0 + x1;
#pragma unroll
    for (int o = 16; o; o >>= 1) s += __shfl_xor_sync(0xffffffffu, s, o);
    if ((tid & 31) == 0) red[tid >> 5] = s;
    __syncthreads();
    if (tid < 8) {
        s = red[tid];
#pragma unroll
        for (int o = 4; o; o >>= 1) s += __shfl_xor_sync(0xffu, s, o);
        if (tid == 0) s_stat[0] = s * (1.0f / DMODEL);
    }
    __syncthreads();
    float mean = s_stat[0];
    float d0 = x0 - mean, d1 = x1 - mean;
    float vv = d0 * d0 + d1 * d1;
#pragma unroll
    for (int o = 16; o; o >>= 1) vv += __shfl_xor_sync(0xffffffffu, vv, o);
    if ((tid & 31) == 0) red[tid >> 5] = vv;
    __syncthreads();
    if (tid < 8) {
        vv = red[tid];
#pragma unroll
        for (int o = 4; o; o >>= 1) vv += __shfl_xor_sync(0xffu, vv, o);
        if (tid == 0) s_stat[1] = rsqrtf(vv * (1.0f / DMODEL) + LN_EPS);
    }
    __syncthreads();
    float inv = s_stat[1];
    h[base + tid]       = d0 * inv * g[tid]       + bb[tid];
    h[base + tid + 256] = d1 * inv * g[tid + 256] + bb[tid + 256];
}

/* ---------------- host driver ---------------- */
#define ATTN_SMEM ((4 * 64 * 68 + 3 * 64) * 4)

extern "C" void kernel_launch(void* const* d_in, const int* in_sizes, int n_in,
                              void* d_out, int out_size) {
    const int*   x    = (const int*)  d_in[0];
    const float* tok  = (const float*)d_in[1];
    const float* pos  = (const float*)d_in[2];
    const float* Wq   = (const float*)d_in[3];
    const float* Wk   = (const float*)d_in[4];
    const float* Wv   = (const float*)d_in[5];
    const float* Wo   = (const float*)d_in[6];
    const float* ln1g = (const float*)d_in[7];
    const float* ln1b = (const float*)d_in[8];
    const float* W1   = (const float*)d_in[9];
    const float* W2   = (const float*)d_in[10];
    const float* ln2g = (const float*)d_in[11];
    const float* ln2b = (const float*)d_in[12];
    const float* Wl   = (const float*)d_in[13];
    float* out = (float*)d_out;

    float *ph, *pq, *pk, *pv, *pa, *pt, *pff;
    cudaGetSymbolAddress((void**)&ph,  g_h);
    cudaGetSymbolAddress((void**)&pq,  g_q);
    cudaGetSymbolAddress((void**)&pk,  g_k);
    cudaGetSymbolAddress((void**)&pv,  g_v);
    cudaGetSymbolAddress((void**)&pa,  g_a);
    cudaGetSymbolAddress((void**)&pt,  g_t);
    cudaGetSymbolAddress((void**)&pff, g_ff);

    cudaFuncSetAttribute(attn_kernel, cudaFuncAttributeMaxDynamicSharedMemorySize, ATTN_SMEM);

    embed_kernel<<<MROWS * DMODEL / 256, 256>>>(x, tok, pos, ph);

    for (int i = 0; i < NDEPTH; i++) {
        const float* wq = Wq + (size_t)i * DMODEL * DMODEL;
        const float* wk = Wk + (size_t)i * DMODEL * DMODEL;
        const float* wv = Wv + (size_t)i * DMODEL * DMODEL;
        const float* wo = Wo + (size_t)i * DMODEL * DMODEL;
        const float* w1 = W1 + (size_t)i * DMODEL * DFFN;
        const float* w2 = W2 + (size_t)i * DFFN * DMODEL;

        gemm_qkv<<<dim3(DMODEL / 128, MROWS / 128, 3), 256, GEMM_SMEM>>>(
            ph, wq, wk, wv, pq, pk, pv, DMODEL, DMODEL);

        l2norm_kernel<<<(2 * MROWS * NHEADS) / 8, 256>>>(pq, pk);

        attn_kernel<<<dim3(SEQ / 64, NHEADS, NB), 256, ATTN_SMEM>>>(pq, pk, pv, pa);

        gemm_tc<0><<<dim3(DMODEL / 128, MROWS / 128), 256, GEMM_SMEM>>>(pa, wo, pt, DMODEL, DMODEL);
        ln_res_kernel<<<MROWS, 256>>>(ph, pt, ln1g + i * DMODEL, ln1b + i * DMODEL);

        gemm_tc<1><<<dim3(DFFN / 128, MROWS / 128), 256, GEMM_SMEM>>>(ph, w1, pff, DFFN, DMODEL);
        gemm_tc<0><<<dim3(DMODEL / 128, MROWS / 128), 256, GEMM_SMEM>>>(pff, w2, pt, DMODEL, DFFN);
        ln_res_kernel<<<MROWS, 256>>>(ph, pt, ln2g + i * DMODEL, ln2b + i * DMODEL);
    }

    gemm_tc<0><<<dim3(VOCAB / 128, MROWS / 128), 256, GEMM_SMEM>>>(ph, Wl, out, VOCAB, DMODEL);
}

// round 3
// speedup vs baseline: 3.0860x; 1.4386x over previous
#include <cuda_runtime.h>
#include <math.h>

#define NB      2
#define SEQ     2048
#define DMODEL  512
#define VOCAB   32000
#define NHEADS  8
#define DHEAD   64
#define DFFN    2048
#define NDEPTH  6
#define MROWS   (NB*SEQ)   /* 4096 */

#define RES_SCALE 1.86120971820393f   /* (2*6)^0.25 */
#define ATTN_SCALE 8.0f
#define LN_EPS 1e-5f

/* ---------------- scratch ---------------- */
__device__ float g_h [MROWS*DMODEL];
__device__ float g_q [MROWS*DMODEL];
__device__ float g_k [MROWS*DMODEL];
__device__ float g_v [MROWS*DMODEL];
__device__ float g_a [MROWS*DMODEL];
__device__ float g_t [MROWS*DMODEL];
__device__ float g_ff[MROWS*DFFN];

__device__ __forceinline__ float tf32r(float x) {
    unsigned u;
    asm("cvt.rna.tf32.f32 %0, %1;" : "=r"(u) : "f"(x));
    return __uint_as_float(u);
}

__device__ __forceinline__ void mma_tf32(float* d, const unsigned* a, unsigned b0, unsigned b1) {
    asm volatile(
        "mma.sync.aligned.m16n8k8.row.col.f32.tf32.tf32.f32 "
        "{%0,%1,%2,%3},{%4,%5,%6,%7},{%8,%9},{%0,%1,%2,%3};"
        : "+f"(d[0]), "+f"(d[1]), "+f"(d[2]), "+f"(d[3])
        : "r"(a[0]), "r"(a[1]), "r"(a[2]), "r"(a[3]), "r"(b0), "r"(b1));
}

/* ---------------- embedding ---------------- */
__global__ void embed_kernel(const int* __restrict__ x, const float* __restrict__ tok,
                             const float* __restrict__ pos, float* __restrict__ h) {
    int idx = blockIdx.x * 256 + threadIdx.x;
    int row = idx >> 9;
    int d   = idx & 511;
    int n   = row & (SEQ - 1);
    h[idx] = tok[x[row] * DMODEL + d] + pos[n * DMODEL + d];
}

/* ================= TF32 tensor-core GEMM (unchanged from R2) ================= */
#define SMB   (16*136)
#define GEMM_SMEM (4*SMB*4)

template<int EPI>
__device__ __forceinline__ void gemm_body(const float* __restrict__ A,
                                          const float* __restrict__ B,
                                          float* __restrict__ C,
                                          int N, int K, float* sm) {
    float* As = sm;
    float* Bs = sm + 2 * SMB;

    int tid  = threadIdx.x;
    int warp = tid >> 5, lane = tid & 31;
    int wm = warp >> 1, wn = warp & 1;
    int g  = lane >> 2, tg = lane & 3;
    int bm = blockIdx.y * 128, bn = blockIdx.x * 128;

    int ar = tid >> 2;
    int ac = (tid & 3) * 4;
    int br = tid >> 5;
    int bc = (tid & 31) * 4;

    const float* Ap = A + (size_t)(bm + ar) * K + ac;
    const float* Bp = B + (size_t)br * N + bn + bc;

    float acc[2][8][4];
#pragma unroll
    for (int i = 0; i < 2; i++)
#pragma unroll
        for (int j = 0; j < 8; j++)
#pragma unroll
            for (int t = 0; t < 4; t++) acc[i][j][t] = 0.0f;

    float4 ra0, ra1, rb0, rb1;
    ra0 = *(const float4*)(Ap);
    ra1 = *(const float4*)(Ap + (size_t)64 * K);
    rb0 = *(const float4*)(Bp);
    rb1 = *(const float4*)(Bp + (size_t)8 * N);

    int nIter = K >> 4;
    int buf = 0;

    {
        float* a0 = As;
        a0[(ac + 0) * 136 + ar]      = tf32r(ra0.x);
        a0[(ac + 1) * 136 + ar]      = tf32r(ra0.y);
        a0[(ac + 2) * 136 + ar]      = tf32r(ra0.z);
        a0[(ac + 3) * 136 + ar]      = tf32r(ra0.w);
        a0[(ac + 0) * 136 + ar + 64] = tf32r(ra1.x);
        a0[(ac + 1) * 136 + ar + 64] = tf32r(ra1.y);
        a0[(ac + 2) * 136 + ar + 64] = tf32r(ra1.z);
        a0[(ac + 3) * 136 + ar + 64] = tf32r(ra1.w);
        float4 c0 = make_float4(tf32r(rb0.x), tf32r(rb0.y), tf32r(rb0.z), tf32r(rb0.w));
        float4 c1 = make_float4(tf32r(rb1.x), tf32r(rb1.y), tf32r(rb1.z), tf32r(rb1.w));
        *(float4*)&Bs[br * 136 + bc]       = c0;
        *(float4*)&Bs[(br + 8) * 136 + bc] = c1;
    }
    __syncthreads();

    for (int it = 0; it < nIter; it++) {
        if (it + 1 < nIter) {
            int k0 = (it + 1) * 16;
            ra0 = *(const float4*)(Ap + k0);
            ra1 = *(const float4*)(Ap + (size_t)64 * K + k0);
            rb0 = *(const float4*)(Bp + (size_t)k0 * N);
            rb1 = *(const float4*)(Bp + (size_t)(k0 + 8) * N);
        }

        const float* a_s = As + buf * SMB;
        const float* b_s = Bs + buf * SMB;
#pragma unroll
        for (int ks = 0; ks < 2; ks++) {
            int k0 = ks * 8;
            unsigned af[2][4];
#pragma unroll
            for (int i = 0; i < 2; i++) {
                int mr = wm * 32 + i * 16 + g;
                af[i][0] = __float_as_uint(a_s[(k0 + tg)     * 136 + mr]);
                af[i][1] = __float_as_uint(a_s[(k0 + tg)     * 136 + mr + 8]);
                af[i][2] = __float_as_uint(a_s[(k0 + tg + 4) * 136 + mr]);
                af[i][3] = __float_as_uint(a_s[(k0 + tg + 4) * 136 + mr + 8]);
            }
#pragma unroll
            for (int j = 0; j < 8; j++) {
                int nc = wn * 64 + j * 8 + g;
                unsigned b0 = __float_as_uint(b_s[(k0 + tg)     * 136 + nc]);
                unsigned b1 = __float_as_uint(b_s[(k0 + tg + 4) * 136 + nc]);
                mma_tf32(acc[0][j], af[0], b0, b1);
                mma_tf32(acc[1][j], af[1], b0, b1);
            }
        }

        if (it + 1 < nIter) {
            float* a_d = As + (buf ^ 1) * SMB;
            a_d[(ac + 0) * 136 + ar]      = tf32r(ra0.x);
            a_d[(ac + 1) * 136 + ar]      = tf32r(ra0.y);
            a_d[(ac + 2) * 136 + ar]      = tf32r(ra0.z);
            a_d[(ac + 3) * 136 + ar]      = tf32r(ra0.w);
            a_d[(ac + 0) * 136 + ar + 64] = tf32r(ra1.x);
            a_d[(ac + 1) * 136 + ar + 64] = tf32r(ra1.y);
            a_d[(ac + 2) * 136 + ar + 64] = tf32r(ra1.z);
            a_d[(ac + 3) * 136 + ar + 64] = tf32r(ra1.w);
            float4 c0 = make_float4(tf32r(rb0.x), tf32r(rb0.y), tf32r(rb0.z), tf32r(rb0.w));
            float4 c1 = make_float4(tf32r(rb1.x), tf32r(rb1.y), tf32r(rb1.z), tf32r(rb1.w));
            *(float4*)&Bs[(buf ^ 1) * SMB + br * 136 + bc]       = c0;
            *(float4*)&Bs[(buf ^ 1) * SMB + (br + 8) * 136 + bc] = c1;
        }
        __syncthreads();
        buf ^= 1;
    }

#pragma unroll
    for (int i = 0; i < 2; i++) {
        int r0 = bm + wm * 32 + i * 16 + g;
#pragma unroll
        for (int j = 0; j < 8; j++) {
            int col = bn + wn * 64 + j * 8 + tg * 2;
            float v0 = acc[i][j][0], v1 = acc[i][j][1];
            float v2 = acc[i][j][2], v3 = acc[i][j][3];
            if (EPI == 1) {
                v0 = 0.5f * v0 * (1.0f + erff(v0 * 0.70710678118654752f));
                v1 = 0.5f * v1 * (1.0f + erff(v1 * 0.70710678118654752f));
                v2 = 0.5f * v2 * (1.0f + erff(v2 * 0.70710678118654752f));
                v3 = 0.5f * v3 * (1.0f + erff(v3 * 0.70710678118654752f));
            }
            *(float2*)&C[(size_t)r0 * N + col]       = make_float2(v0, v1);
            *(float2*)&C[(size_t)(r0 + 8) * N + col] = make_float2(v2, v3);
        }
    }
}

template<int EPI>
__global__ __launch_bounds__(256) void gemm_tc(const float* __restrict__ A,
                                               const float* __restrict__ B,
                                               float* __restrict__ C, int N, int K) {
    extern __shared__ float sm[];
    gemm_body<EPI>(A, B, C, N, K, sm);
}

__global__ __launch_bounds__(256) void gemm_qkv(const float* __restrict__ A,
                                                const float* __restrict__ B0,
                                                const float* __restrict__ B1,
                                                const float* __restrict__ B2,
                                                float* __restrict__ C0,
                                                float* __restrict__ C1,
                                                float* __restrict__ C2,
                                                int N, int K) {
    extern __shared__ float sm[];
    const float* B = (blockIdx.z == 0) ? B0 : (blockIdx.z == 1) ? B1 : B2;
    float*       C = (blockIdx.z == 0) ? C0 : (blockIdx.z == 1) ? C1 : C2;
    gemm_body<0>(A, B, C, N, K, sm);
}

/* ---------------- per-head L2 normalize of q,k ---------------- */
__global__ void l2norm_kernel(float* __restrict__ q, float* __restrict__ k) {
    int w    = (blockIdx.x * blockDim.x + threadIdx.x) >> 5;
    int lane = threadIdx.x & 31;
    float* base = (w < MROWS * NHEADS) ? (q + (size_t)w * 64)
                                       : (k + (size_t)(w - MROWS * NHEADS) * 64);
    float a = base[lane], c = base[lane + 32];
    float ss = a * a + c * c;
#pragma unroll
    for (int o = 16; o; o >>= 1) ss += __shfl_xor_sync(0xffffffffu, ss, o);
    float inv = 1.0f / fmaxf(sqrtf(ss), 1e-12f);
    base[lane]      = a * inv;
    base[lane + 32] = c * inv;
}

/* ================= TF32 tensor-core flash attention =================
   CTA: 128 thr (4 warps), 64 q-rows; warp owns 16 rows. 64-key tiles.
   Ks: [64 d][72] d-major, key index XOR-swizzled by (d>>2)&7.
   Vs: [64 key][72] key-major. Ps: [64 row][72] per-warp P round-trip. */
#define APAD 72
#define ATTN_SMEM (3 * 64 * APAD * 4)

__global__ __launch_bounds__(128) void attn_tc(const float* __restrict__ q,
                                               const float* __restrict__ k,
                                               const float* __restrict__ v,
                                               float* __restrict__ o) {
    extern __shared__ float sm[];
    float* Ks = sm;
    float* Vs = sm + 64 * APAD;
    float* Ps = sm + 2 * 64 * APAD;

    int qt = gridDim.x - 1 - blockIdx.x;   /* longest CTAs first */
    int hh = blockIdx.y, b = blockIdx.z;
    int tid = threadIdx.x, warp = tid >> 5, lane = tid & 31;
    int g = lane >> 2, tg = lane & 3;

    /* Q fragments resident in registers for whole kernel */
    unsigned qf[8][4];
    const float* qbase = q + (size_t)(b * SEQ + qt * 64 + warp * 16 + g) * DMODEL + hh * 64;
#pragma unroll
    for (int kk = 0; kk < 8; kk++) {
        qf[kk][0] = __float_as_uint(tf32r(qbase[kk * 8 + tg]));
        qf[kk][1] = __float_as_uint(tf32r(qbase[(size_t)8 * DMODEL + kk * 8 + tg]));
        qf[kk][2] = __float_as_uint(tf32r(qbase[kk * 8 + tg + 4]));
        qf[kk][3] = __float_as_uint(tf32r(qbase[(size_t)8 * DMODEL + kk * 8 + tg + 4]));
    }

    float oa[8][4];
#pragma unroll
    for (int j = 0; j < 8; j++)
#pragma unroll
        for (int t = 0; t < 4; t++) oa[j][t] = 0.0f;
    float m0 = -1e30f, m1 = -1e30f, l0 = 0.0f, l1 = 0.0f;

    int prow0 = (warp * 16 + g) * APAD;
    int prow1 = (warp * 16 + g + 8) * APAD;

    for (int kt = 0; kt <= qt; kt++) {
        __syncthreads();
        /* stage K (transposed, swizzled) and V (tf32-rounded) */
        for (int i = tid; i < 1024; i += 128) {
            int r  = i >> 4;
            int c4 = (i & 15) * 4;
            size_t gg = (size_t)(b * SEQ + kt * 64 + r) * DMODEL + hh * 64 + c4;
            float4 k4 = *(const float4*)(k + gg);
            int rk = r ^ ((c4 >> 2) & 7);
            Ks[(c4 + 0) * APAD + rk] = tf32r(k4.x);
            Ks[(c4 + 1) * APAD + rk] = tf32r(k4.y);
            Ks[(c4 + 2) * APAD + rk] = tf32r(k4.z);
            Ks[(c4 + 3) * APAD + rk] = tf32r(k4.w);
            float4 v4 = *(const float4*)(v + gg);
            Vs[r * APAD + c4 + 0] = tf32r(v4.x);
            Vs[r * APAD + c4 + 1] = tf32r(v4.y);
            Vs[r * APAD + c4 + 2] = tf32r(v4.z);
            Vs[r * APAD + c4 + 3] = tf32r(v4.w);
        }
        __syncthreads();

        /* S = Q K^T */
        float s[8][4];
#pragma unroll
        for (int j = 0; j < 8; j++)
#pragma unroll
            for (int t = 0; t < 4; t++) s[j][t] = 0.0f;
#pragma unroll
        for (int kk = 0; kk < 8; kk++) {
            int d0 = kk * 8 + tg, d1 = d0 + 4;
            int sw0 = (d0 >> 2) & 7, sw1 = (d1 >> 2) & 7;
#pragma unroll
            for (int j = 0; j < 8; j++) {
                unsigned b0 = __float_as_uint(Ks[d0 * APAD + ((j * 8 + g) ^ sw0)]);
                unsigned b1 = __float_as_uint(Ks[d1 * APAD + ((j * 8 + g) ^ sw1)]);
                mma_tf32(s[j], qf[kk], b0, b1);
            }
        }

        /* scale + causal mask (only diagonal tile) */
        if (kt == qt) {
            int r0 = warp * 16 + g, r1 = r0 + 8;
#pragma unroll
            for (int j = 0; j < 8; j++) {
                int c0 = j * 8 + tg * 2, c1 = c0 + 1;
                s[j][0] = (c0 > r0) ? -1e30f : s[j][0] * ATTN_SCALE;
                s[j][1] = (c1 > r0) ? -1e30f : s[j][1] * ATTN_SCALE;
                s[j][2] = (c0 > r1) ? -1e30f : s[j][2] * ATTN_SCALE;
                s[j][3] = (c1 > r1) ? -1e30f : s[j][3] * ATTN_SCALE;
            }
        } else {
#pragma unroll
            for (int j = 0; j < 8; j++)
#pragma unroll
                for (int t = 0; t < 4; t++) s[j][t] *= ATTN_SCALE;
        }

        /* row max across frags + 4 lanes */
        float rx0 = -1e30f, rx1 = -1e30f;
#pragma unroll
        for (int j = 0; j < 8; j++) {
            rx0 = fmaxf(rx0, fmaxf(s[j][0], s[j][1]));
            rx1 = fmaxf(rx1, fmaxf(s[j][2], s[j][3]));
        }
        rx0 = fmaxf(rx0, __shfl_xor_sync(0xffffffffu, rx0, 1));
        rx0 = fmaxf(rx0, __shfl_xor_sync(0xffffffffu, rx0, 2));
        rx1 = fmaxf(rx1, __shfl_xor_sync(0xffffffffu, rx1, 1));
        rx1 = fmaxf(rx1, __shfl_xor_sync(0xffffffffu, rx1, 2));

        float mn0 = fmaxf(m0, rx0), mn1 = fmaxf(m1, rx1);
        float cr0 = __expf(m0 - mn0), cr1 = __expf(m1 - mn1);

        float sum0 = 0.0f, sum1 = 0.0f;
#pragma unroll
        for (int j = 0; j < 8; j++) {
            int c0 = j * 8 + tg * 2;
            float e0 = __expf(s[j][0] - mn0);
            float e1 = __expf(s[j][1] - mn0);
            float e2 = __expf(s[j][2] - mn1);
            float e3 = __expf(s[j][3] - mn1);
            sum0 += e0 + e1;
            sum1 += e2 + e3;
            *(float2*)&Ps[prow0 + c0] = make_float2(e0, e1);
            *(float2*)&Ps[prow1 + c0] = make_float2(e2, e3);
        }
        sum0 += __shfl_xor_sync(0xffffffffu, sum0, 1);
        sum0 += __shfl_xor_sync(0xffffffffu, sum0, 2);
        sum1 += __shfl_xor_sync(0xffffffffu, sum1, 1);
        sum1 += __shfl_xor_sync(0xffffffffu, sum1, 2);

        m0 = mn0; m1 = mn1;
        l0 = l0 * cr0 + sum0;
        l1 = l1 * cr1 + sum1;

#pragma unroll
        for (int j = 0; j < 8; j++) {
            oa[j][0] *= cr0; oa[j][1] *= cr0;
            oa[j][2] *= cr1; oa[j][3] *= cr1;
        }
        __syncwarp();

        /* O += P V */
#pragma unroll
        for (int kk = 0; kk < 8; kk++) {
            unsigned a[4];
            a[0] = __float_as_uint(Ps[prow0 + kk * 8 + tg]);
            a[1] = __float_as_uint(Ps[prow1 + kk * 8 + tg]);
            a[2] = __float_as_uint(Ps[prow0 + kk * 8 + tg + 4]);
            a[3] = __float_as_uint(Ps[prow1 + kk * 8 + tg + 4]);
#pragma unroll
            for (int j = 0; j < 8; j++) {
                unsigned b0 = __float_as_uint(Vs[(kk * 8 + tg)     * APAD + j * 8 + g]);
                unsigned b1 = __float_as_uint(Vs[(kk * 8 + tg + 4) * APAD + j * 8 + g]);
                mma_tf32(oa[j], a, b0, b1);
            }
        }
        __syncwarp();
    }

    /* epilogue */
    float inv0 = 1.0f / l0, inv1 = 1.0f / l1;
    size_t orow0 = (size_t)(b * SEQ + qt * 64 + warp * 16 + g) * DMODEL + hh * 64;
    size_t orow1 = orow0 + (size_t)8 * DMODEL;
#pragma unroll
    for (int j = 0; j < 8; j++) {
        int c0 = j * 8 + tg * 2;
        *(float2*)&o[orow0 + c0] = make_float2(oa[j][0] * inv0, oa[j][1] * inv0);
        *(float2*)&o[orow1 + c0] = make_float2(oa[j][2] * inv1, oa[j][3] * inv1);
    }
}

/* ---------------- fused residual + LayerNorm ---------------- */
__global__ void ln_res_kernel(float* __restrict__ h, const float* __restrict__ a,
                              const float* __restrict__ g, const float* __restrict__ bb) {
    __shared__ float red[8];
    __shared__ float s_stat[2];
    int row = blockIdx.x, tid = threadIdx.x;
    size_t base = (size_t)row * DMODEL;
    float x0 = fmaf(RES_SCALE, h[base + tid],       a[base + tid]);
    float x1 = fmaf(RES_SCALE, h[base + tid + 256], a[base + tid + 256]);

    float s = x0 + x1;
#pragma unroll
    for (int o = 16; o; o >>= 1) s += __shfl_xor_sync(0xffffffffu, s, o);
    if ((tid & 31) == 0) red[tid >> 5] = s;
    __syncthreads();
    if (tid < 8) {
        s = red[tid];
#pragma unroll
        for (int o = 4; o; o >>= 1) s += __shfl_xor_sync(0xffu, s, o);
        if (tid == 0) s_stat[0] = s * (1.0f / DMODEL);
    }
    __syncthreads();
    float mean = s_stat[0];
    float d0 = x0 - mean, d1 = x1 - mean;
    float vv = d0 * d0 + d1 * d1;
#pragma unroll
    for (int o = 16; o; o >>= 1) vv += __shfl_xor_sync(0xffffffffu, vv, o);
    if ((tid & 31) == 0) red[tid >> 5] = vv;
    __syncthreads();
    if (tid < 8) {
        vv = red[tid];
#pragma unroll
        for (int o = 4; o; o >>= 1) vv += __shfl_xor_sync(0xffu, vv, o);
        if (tid == 0) s_stat[1] = rsqrtf(vv * (1.0f / DMODEL) + LN_EPS);
    }
    __syncthreads();
    float inv = s_stat[1];
    h[base + tid]       = d0 * inv * g[tid]       + bb[tid];
    h[base + tid + 256] = d1 * inv * g[tid + 256] + bb[tid + 256];
}

/* ---------------- host driver ---------------- */
extern "C" void kernel_launch(void* const* d_in, const int* in_sizes, int n_in,
                              void* d_out, int out_size) {
    const int*   x    = (const int*)  d_in[0];
    const float* tok  = (const float*)d_in[1];
    const float* pos  = (const float*)d_in[2];
    const float* Wq   = (const float*)d_in[3];
    const float* Wk   = (const float*)d_in[4];
    const float* Wv   = (const float*)d_in[5];
    const float* Wo   = (const float*)d_in[6];
    const float* ln1g = (const float*)d_in[7];
    const float* ln1b = (const float*)d_in[8];
    const float* W1   = (const float*)d_in[9];
    const float* W2   = (const float*)d_in[10];
    const float* ln2g = (const float*)d_in[11];
    const float* ln2b = (const float*)d_in[12];
    const float* Wl   = (const float*)d_in[13];
    float* out = (float*)d_out;

    float *ph, *pq, *pk, *pv, *pa, *pt, *pff;
    cudaGetSymbolAddress((void**)&ph,  g_h);
    cudaGetSymbolAddress((void**)&pq,  g_q);
    cudaGetSymbolAddress((void**)&pk,  g_k);
    cudaGetSymbolAddress((void**)&pv,  g_v);
    cudaGetSymbolAddress((void**)&pa,  g_a);
    cudaGetSymbolAddress((void**)&pt,  g_t);
    cudaGetSymbolAddress((void**)&pff, g_ff);

    cudaFuncSetAttribute(attn_tc, cudaFuncAttributeMaxDynamicSharedMemorySize, ATTN_SMEM);

    embed_kernel<<<MROWS * DMODEL / 256, 256>>>(x, tok, pos, ph);

    for (int i = 0; i < NDEPTH; i++) {
        const float* wq = Wq + (size_t)i * DMODEL * DMODEL;
        const float* wk = Wk + (size_t)i * DMODEL * DMODEL;
        const float* wv = Wv + (size_t)i * DMODEL * DMODEL;
        const float* wo = Wo + (size_t)i * DMODEL * DMODEL;
        const float* w1 = W1 + (size_t)i * DMODEL * DFFN;
        const float* w2 = W2 + (size_t)i * DFFN * DMODEL;

        gemm_qkv<<<dim3(DMODEL / 128, MROWS / 128, 3), 256, GEMM_SMEM>>>(
            ph, wq, wk, wv, pq, pk, pv, DMODEL, DMODEL);

        l2norm_kernel<<<(2 * MROWS * NHEADS) / 8, 256>>>(pq, pk);

        attn_tc<<<dim3(SEQ / 64, NHEADS, NB), 128, ATTN_SMEM>>>(pq, pk, pv, pa);

        gemm_tc<0><<<dim3(DMODEL / 128, MROWS / 128), 256, GEMM_SMEM>>>(pa, wo, pt, DMODEL, DMODEL);
        ln_res_kernel<<<MROWS, 256>>>(ph, pt, ln1g + i * DMODEL, ln1b + i * DMODEL);

        gemm_tc<1><<<dim3(DFFN / 128, MROWS / 128), 256, GEMM_SMEM>>>(ph, w1, pff, DFFN, DMODEL);
        gemm_tc<0><<<dim3(DMODEL / 128, MROWS / 128), 256, GEMM_SMEM>>>(pff, w2, pt, DMODEL, DFFN);
        ln_res_kernel<<<MROWS, 256>>>(ph, pt, ln2g + i * DMODEL, ln2b + i * DMODEL);
    }

    gemm_tc<0><<<dim3(VOCAB / 128, MROWS / 128), 256, GEMM_SMEM>>>(ph, Wl, out, VOCAB, DMODEL);
}

// round 5
// speedup vs baseline: 3.4449x; 1.1163x over previous
#include <cuda_runtime.h>
#include <cuda_bf16.h>
#include <math.h>
#include <stdint.h>

#define NB      2
#define SEQ     2048
#define DMODEL  512
#define VOCAB   32000
#define NHEADS  8
#define DHEAD   64
#define DFFN    2048
#define NDEPTH  6
#define MROWS   (NB*SEQ)   /* 4096 */

#define RES_SCALE 1.86120971820393f
#define ATTN_SCALE 8.0f
#define LN_EPS 1e-5f

/* ---------------- scratch ---------------- */
__device__ float g_h [MROWS*DMODEL];
__device__ float g_q [MROWS*DMODEL];
__device__ float g_k [MROWS*DMODEL];
__device__ float g_v [MROWS*DMODEL];
__device__ float g_a [MROWS*DMODEL];
__device__ float g_t [MROWS*DMODEL];
__device__ float g_ff[MROWS*DFFN];
/* tf32-rounded weights: Wq|Wk|Wv|Wo (4x 1572864) | W1 (6291456) | W2 (6291456) | Wl (16384000) */
#define WOFF_Q  0
#define WOFF_K  1572864
#define WOFF_V  3145728
#define WOFF_O  4718592
#define WOFF_1  6291456
#define WOFF_2  12582912
#define WOFF_L  18874368
#define WTOTAL  35258368
__device__ float g_w[WTOTAL];

__device__ __forceinline__ float tf32r(float x) {
    unsigned u;
    asm("cvt.rna.tf32.f32 %0, %1;" : "=r"(u) : "f"(x));
    return __uint_as_float(u);
}
__device__ __forceinline__ uint32_t smem_u32(const void* p) {
    uint32_t a;
    asm("{ .reg .u64 t; cvta.to.shared.u64 t, %1; cvt.u32.u64 %0, t; }" : "=r"(a) : "l"(p));
    return a;
}
__device__ __forceinline__ void cpa16(uint32_t dst, const void* src) {
    asm volatile("cp.async.cg.shared.global [%0], [%1], 16;" :: "r"(dst), "l"(src));
}
__device__ __forceinline__ void mma_tf32(float* d, const unsigned* a, unsigned b0, unsigned b1) {
    asm volatile(
        "mma.sync.aligned.m16n8k8.row.col.f32.tf32.tf32.f32 "
        "{%0,%1,%2,%3},{%4,%5,%6,%7},{%8,%9},{%0,%1,%2,%3};"
        : "+f"(d[0]), "+f"(d[1]), "+f"(d[2]), "+f"(d[3])
        : "r"(a[0]), "r"(a[1]), "r"(a[2]), "r"(a[3]), "r"(b0), "r"(b1));
}

/* ---------------- weight pre-round ---------------- */
__global__ void round_copy(const float* __restrict__ src, float* __restrict__ dst, int n) {
    int i = blockIdx.x * 256 + threadIdx.x;
    if (i < n) dst[i] = tf32r(src[i]);
}

/* ---------------- embedding (tf32-rounded output) ---------------- */
__global__ void embed_kernel(const int* __restrict__ x, const float* __restrict__ tok,
                             const float* __restrict__ pos, float* __restrict__ h) {
    int idx = blockIdx.x * 256 + threadIdx.x;
    int row = idx >> 9;
    int d   = idx & 511;
    int n   = row & (SEQ - 1);
    h[idx] = tf32r(tok[x[row] * DMODEL + d] + pos[n * DMODEL + d]);
}

/* ================= TF32 mma.sync GEMM, cp.async 3-stage =================
   C[MxN] = A[MxK]*B[KxN], row-major, inputs already tf32-rounded.
   BM=BN=128, BK=32, 256 thr = 8 warps (4x2), warp tile 32x64.
   As: [128][36] row-major (bank-clean frag reads).
   Bs: [32][128] with 16B-chunk XOR swizzle cn ^= 2*(k&3) (bank-clean). */
#define AST     36
#define ASTAGE  (128*AST)            /* 4608 floats */
#define BSTAGE  (32*128)             /* 4096 floats */
#define STAGE_F (ASTAGE+BSTAGE)      /* 8704 floats */
#define G_SMEM  (3*STAGE_F*4)        /* 104448 B */

/* EPI: 0 = none, 1 = exact GELU + tf32 round (FF1) */
template<int EPI>
__device__ __forceinline__ void gemm_body(const float* __restrict__ A,
                                          const float* __restrict__ B,
                                          float* __restrict__ C,
                                          int N, int K, float* sm) {
    int tid = threadIdx.x;
    int warp = tid >> 5, lane = tid & 31;
    int wm = warp >> 1, wn = warp & 1;
    int g = lane >> 2, tg = lane & 3;
    int bm = blockIdx.y * 128, bn = blockIdx.x * 128;

    uint32_t sb = smem_u32(sm);

    /* per-thread staging coords */
    int a_r = tid >> 1;               /* A: 256 thr x 2 chunks: row=tid>>1, c4=(tid&1)*16.. wait */
    /* A stage: 128 rows x 32 floats = 1024 x 16B chunks; thread does 4 chunks */
    /* B stage: 32 rows x 128 floats = 1024 chunks; thread does 4 chunks */

    float acc[2][8][4];
#pragma unroll
    for (int i = 0; i < 2; i++)
#pragma unroll
        for (int j = 0; j < 8; j++)
#pragma unroll
            for (int t = 0; t < 4; t++) acc[i][j][t] = 0.0f;

    int nIter = K >> 5;

    /* ---- stage issue lambda-ish macro ---- */
#define STAGE(slot, k0)                                                          \
    do {                                                                         \
        uint32_t as_ = sb + (uint32_t)(slot) * (STAGE_F * 4);                    \
        uint32_t bs_ = as_ + ASTAGE * 4;                                         \
        _Pragma("unroll")                                                        \
        for (int it_ = 0; it_ < 4; it_++) {                                      \
            int id_ = tid + it_ * 256;                                           \
            int r_ = id_ >> 3, c4_ = (id_ & 7) * 4;                              \
            cpa16(as_ + (r_ * AST + c4_) * 4,                                    \
                  A + (size_t)(bm + r_) * K + (k0) + c4_);                       \
        }                                                                        \
        _Pragma("unroll")                                                        \
        for (int it_ = 0; it_ < 4; it_++) {                                      \
            int id_ = tid + it_ * 256;                                           \
            int r_ = id_ >> 5, cn_ = id_ & 31;                                   \
            int pc_ = cn_ ^ ((r_ & 3) << 1);                                     \
            cpa16(bs_ + (r_ * 128 + pc_ * 4) * 4,                                \
                  B + (size_t)((k0) + r_) * N + bn + cn_ * 4);                   \
        }                                                                        \
        asm volatile("cp.async.commit_group;" ::: "memory");                     \
    } while (0)

    STAGE(0, 0);
    if (nIter > 1) STAGE(1, 32);
    else asm volatile("cp.async.commit_group;" ::: "memory");

    for (int it = 0; it < nIter; it++) {
        asm volatile("cp.async.wait_group 1;" ::: "memory");
        __syncthreads();

        int slot = it % 3;
        const float* as = sm + slot * STAGE_F;
        const float* bs = as + ASTAGE;

#pragma unroll
        for (int ks = 0; ks < 4; ks++) {
            int k8 = ks * 8;
            unsigned af[2][4];
#pragma unroll
            for (int i = 0; i < 2; i++) {
                int mr = wm * 32 + i * 16 + g;
                af[i][0] = __float_as_uint(as[mr * AST + k8 + tg]);
                af[i][1] = __float_as_uint(as[(mr + 8) * AST + k8 + tg]);
                af[i][2] = __float_as_uint(as[mr * AST + k8 + tg + 4]);
                af[i][3] = __float_as_uint(as[(mr + 8) * AST + k8 + tg + 4]);
            }
#pragma unroll
            for (int j = 0; j < 8; j++) {
                int nc = wn * 64 + j * 8 + g;
                int phys = ((nc >> 2) ^ (tg << 1)) * 4 + (nc & 3);
                unsigned b0 = __float_as_uint(bs[(k8 + tg) * 128 + phys]);
                unsigned b1 = __float_as_uint(bs[(k8 + tg + 4) * 128 + phys]);
                mma_tf32(acc[0][j], af[0], b0, b1);
                mma_tf32(acc[1][j], af[1], b0, b1);
            }
        }
        __syncthreads();
        if (it + 2 < nIter) STAGE((it + 2) % 3, (it + 2) * 32);
        else asm volatile("cp.async.commit_group;" ::: "memory");
    }
#undef STAGE

    /* epilogue */
#pragma unroll
    for (int i = 0; i < 2; i++) {
        int r0 = bm + wm * 32 + i * 16 + g;
#pragma unroll
        for (int j = 0; j < 8; j++) {
            int col = bn + wn * 64 + j * 8 + tg * 2;
            float v0 = acc[i][j][0], v1 = acc[i][j][1];
            float v2 = acc[i][j][2], v3 = acc[i][j][3];
            if (EPI == 1) {
                v0 = tf32r(0.5f * v0 * (1.0f + erff(v0 * 0.70710678118654752f)));
                v1 = tf32r(0.5f * v1 * (1.0f + erff(v1 * 0.70710678118654752f)));
                v2 = tf32r(0.5f * v2 * (1.0f + erff(v2 * 0.70710678118654752f)));
                v3 = tf32r(0.5f * v3 * (1.0f + erff(v3 * 0.70710678118654752f)));
            }
            *(float2*)&C[(size_t)r0 * N + col]       = make_float2(v0, v1);
            *(float2*)&C[(size_t)(r0 + 8) * N + col] = make_float2(v2, v3);
        }
    }
}

template<int EPI>
__global__ __launch_bounds__(256) void gemm_tc(const float* __restrict__ A,
                                               const float* __restrict__ B,
                                               float* __restrict__ C, int N, int K) {
    extern __shared__ float sm[];
    gemm_body<EPI>(A, B, C, N, K, sm);
}

__global__ __launch_bounds__(256) void gemm_qkv(const float* __restrict__ A,
                                                const float* __restrict__ B0,
                                                const float* __restrict__ B1,
                                                const float* __restrict__ B2,
                                                float* __restrict__ C0,
                                                float* __restrict__ C1,
                                                float* __restrict__ C2,
                                                int N, int K) {
    extern __shared__ float sm[];
    const float* B = (blockIdx.z == 0) ? B0 : (blockIdx.z == 1) ? B1 : B2;
    float*       C = (blockIdx.z == 0) ? C0 : (blockIdx.z == 1) ? C1 : C2;
    gemm_body<0>(A, B, C, N, K, sm);
}

/* ---------------- per-head L2 normalize of q,k ---------------- */
__global__ void l2norm_kernel(float* __restrict__ q, float* __restrict__ k) {
    int w    = (blockIdx.x * blockDim.x + threadIdx.x) >> 5;
    int lane = threadIdx.x & 31;
    float* base = (w < MROWS * NHEADS) ? (q + (size_t)w * 64)
                                       : (k + (size_t)(w - MROWS * NHEADS) * 64);
    float a = base[lane], c = base[lane + 32];
    float ss = a * a + c * c;
#pragma unroll
    for (int o = 16; o; o >>= 1) ss += __shfl_xor_sync(0xffffffffu, ss, o);
    float inv = 1.0f / fmaxf(sqrtf(ss), 1e-12f);
    base[lane]      = a * inv;
    base[lane + 32] = c * inv;
}

/* ================= TF32 tensor-core flash attention (R3, unchanged except
   tf32-rounded output stores) ================= */
#define APAD 72
#define ATTN_SMEM (3 * 64 * APAD * 4)

__global__ __launch_bounds__(128) void attn_tc(const float* __restrict__ q,
                                               const float* __restrict__ k,
                                               const float* __restrict__ v,
                                               float* __restrict__ o) {
    extern __shared__ float sm[];
    float* Ks = sm;
    float* Vs = sm + 64 * APAD;
    float* Ps = sm + 2 * 64 * APAD;

    int qt = gridDim.x - 1 - blockIdx.x;
    int hh = blockIdx.y, b = blockIdx.z;
    int tid = threadIdx.x, warp = tid >> 5, lane = tid & 31;
    int g = lane >> 2, tg = lane & 3;

    unsigned qf[8][4];
    const float* qbase = q + (size_t)(b * SEQ + qt * 64 + warp * 16 + g) * DMODEL + hh * 64;
#pragma unroll
    for (int kk = 0; kk < 8; kk++) {
        qf[kk][0] = __float_as_uint(tf32r(qbase[kk * 8 + tg]));
        qf[kk][1] = __float_as_uint(tf32r(qbase[(size_t)8 * DMODEL + kk * 8 + tg]));
        qf[kk][2] = __float_as_uint(tf32r(qbase[kk * 8 + tg + 4]));
        qf[kk][3] = __float_as_uint(tf32r(qbase[(size_t)8 * DMODEL + kk * 8 + tg + 4]));
    }

    float oa[8][4];
#pragma unroll
    for (int j = 0; j < 8; j++)
#pragma unroll
        for (int t = 0; t < 4; t++) oa[j][t] = 0.0f;
    float m0 = -1e30f, m1 = -1e30f, l0 = 0.0f, l1 = 0.0f;

    int prow0 = (warp * 16 + g) * APAD;
    int prow1 = (warp * 16 + g + 8) * APAD;

    for (int kt = 0; kt <= qt; kt++) {
        __syncthreads();
        for (int i = tid; i < 1024; i += 128) {
            int r  = i >> 4;
            int c4 = (i & 15) * 4;
            size_t gg = (size_t)(b * SEQ + kt * 64 + r) * DMODEL + hh * 64 + c4;
            float4 k4 = *(const float4*)(k + gg);
            int rk = r ^ ((c4 >> 2) & 7);
            Ks[(c4 + 0) * APAD + rk] = tf32r(k4.x);
            Ks[(c4 + 1) * APAD + rk] = tf32r(k4.y);
            Ks[(c4 + 2) * APAD + rk] = tf32r(k4.z);
            Ks[(c4 + 3) * APAD + rk] = tf32r(k4.w);
            float4 v4 = *(const float4*)(v + gg);
            Vs[r * APAD + c4 + 0] = tf32r(v4.x);
            Vs[r * APAD + c4 + 1] = tf32r(v4.y);
            Vs[r * APAD + c4 + 2] = tf32r(v4.z);
            Vs[r * APAD + c4 + 3] = tf32r(v4.w);
        }
        __syncthreads();

        float s[8][4];
#pragma unroll
        for (int j = 0; j < 8; j++)
#pragma unroll
            for (int t = 0; t < 4; t++) s[j][t] = 0.0f;
#pragma unroll
        for (int kk = 0; kk < 8; kk++) {
            int d0 = kk * 8 + tg, d1 = d0 + 4;
            int sw0 = (d0 >> 2) & 7, sw1 = (d1 >> 2) & 7;
#pragma unroll
            for (int j = 0; j < 8; j++) {
                unsigned b0 = __float_as_uint(Ks[d0 * APAD + ((j * 8 + g) ^ sw0)]);
                unsigned b1 = __float_as_uint(Ks[d1 * APAD + ((j * 8 + g) ^ sw1)]);
                mma_tf32(s[j], qf[kk], b0, b1);
            }
        }

        if (kt == qt) {
            int r0 = warp * 16 + g, r1 = r0 + 8;
#pragma unroll
            for (int j = 0; j < 8; j++) {
                int c0 = j * 8 + tg * 2, c1 = c0 + 1;
                s[j][0] = (c0 > r0) ? -1e30f : s[j][0] * ATTN_SCALE;
                s[j][1] = (c1 > r0) ? -1e30f : s[j][1] * ATTN_SCALE;
                s[j][2] = (c0 > r1) ? -1e30f : s[j][2] * ATTN_SCALE;
                s[j][3] = (c1 > r1) ? -1e30f : s[j][3] * ATTN_SCALE;
            }
        } else {
#pragma unroll
            for (int j = 0; j < 8; j++)
#pragma unroll
                for (int t = 0; t < 4; t++) s[j][t] *= ATTN_SCALE;
        }

        float rx0 = -1e30f, rx1 = -1e30f;
#pragma unroll
        for (int j = 0; j < 8; j++) {
            rx0 = fmaxf(rx0, fmaxf(s[j][0], s[j][1]));
            rx1 = fmaxf(rx1, fmaxf(s[j][2], s[j][3]));
        }
        rx0 = fmaxf(rx0, __shfl_xor_sync(0xffffffffu, rx0, 1));
        rx0 = fmaxf(rx0, __shfl_xor_sync(0xffffffffu, rx0, 2));
        rx1 = fmaxf(rx1, __shfl_xor_sync(0xffffffffu, rx1, 1));
        rx1 = fmaxf(rx1, __shfl_xor_sync(0xffffffffu, rx1, 2));

        float mn0 = fmaxf(m0, rx0), mn1 = fmaxf(m1, rx1);
        float cr0 = __expf(m0 - mn0), cr1 = __expf(m1 - mn1);

        float sum0 = 0.0f, sum1 = 0.0f;
#pragma unroll
        for (int j = 0; j < 8; j++) {
            int c0 = j * 8 + tg * 2;
            float e0 = __expf(s[j][0] - mn0);
            float e1 = __expf(s[j][1] - mn0);
            float e2 = __expf(s[j][2] - mn1);
            float e3 = __expf(s[j][3] - mn1);
            sum0 += e0 + e1;
            sum1 += e2 + e3;
            *(float2*)&Ps[prow0 + c0] = make_float2(e0, e1);
            *(float2*)&Ps[prow1 + c0] = make_float2(e2, e3);
        }
        sum0 += __shfl_xor_sync(0xffffffffu, sum0, 1);
        sum0 += __shfl_xor_sync(0xffffffffu, sum0, 2);
        sum1 += __shfl_xor_sync(0xffffffffu, sum1, 1);
        sum1 += __shfl_xor_sync(0xffffffffu, sum1, 2);

        m0 = mn0; m1 = mn1;
        l0 = l0 * cr0 + sum0;
        l1 = l1 * cr1 + sum1;

#pragma unroll
        for (int j = 0; j < 8; j++) {
            oa[j][0] *= cr0; oa[j][1] *= cr0;
            oa[j][2] *= cr1; oa[j][3] *= cr1;
        }
        __syncwarp();

#pragma unroll
        for (int kk = 0; kk < 8; kk++) {
            unsigned a[4];
            a[0] = __float_as_uint(Ps[prow0 + kk * 8 + tg]);
            a[1] = __float_as_uint(Ps[prow1 + kk * 8 + tg]);
            a[2] = __float_as_uint(Ps[prow0 + kk * 8 + tg + 4]);
            a[3] = __float_as_uint(Ps[prow1 + kk * 8 + tg + 4]);
#pragma unroll
            for (int j = 0; j < 8; j++) {
                unsigned b0 = __float_as_uint(Vs[(kk * 8 + tg)     * APAD + j * 8 + g]);
                unsigned b1 = __float_as_uint(Vs[(kk * 8 + tg + 4) * APAD + j * 8 + g]);
                mma_tf32(oa[j], a, b0, b1);
            }
        }
        __syncwarp();
    }

    float inv0 = 1.0f / l0, inv1 = 1.0f / l1;
    size_t orow0 = (size_t)(b * SEQ + qt * 64 + warp * 16 + g) * DMODEL + hh * 64;
    size_t orow1 = orow0 + (size_t)8 * DMODEL;
#pragma unroll
    for (int j = 0; j < 8; j++) {
        int c0 = j * 8 + tg * 2;
        *(float2*)&o[orow0 + c0] = make_float2(tf32r(oa[j][0] * inv0), tf32r(oa[j][1] * inv0));
        *(float2*)&o[orow1 + c0] = make_float2(tf32r(oa[j][2] * inv1), tf32r(oa[j][3] * inv1));
    }
}

/* ---------------- fused residual + LayerNorm (tf32-rounded output) -------- */
__global__ void ln_res_kernel(float* __restrict__ h, const float* __restrict__ a,
                              const float* __restrict__ g, const float* __restrict__ bb) {
    __shared__ float red[8];
    __shared__ float s_stat[2];
    int row = blockIdx.x, tid = threadIdx.x;
    size_t base = (size_t)row * DMODEL;
    float x0 = fmaf(RES_SCALE, h[base + tid],       a[base + tid]);
    float x1 = fmaf(RES_SCALE, h[base + tid + 256], a[base + tid + 256]);

    float s = x0 + x1;
#pragma unroll
    for (int o = 16; o; o >>= 1) s += __shfl_xor_sync(0xffffffffu, s, o);
    if ((tid & 31) == 0) red[tid >> 5] = s;
    __syncthreads();
    if (tid < 8) {
        s = red[tid];
#pragma unroll
        for (int o = 4; o; o >>= 1) s += __shfl_xor_sync(0xffu, s, o);
        if (tid == 0) s_stat[0] = s * (1.0f / DMODEL);
    }
    __syncthreads();
    float mean = s_stat[0];
    float d0 = x0 - mean, d1 = x1 - mean;
    float vv = d0 * d0 + d1 * d1;
#pragma unroll
    for (int o = 16; o; o >>= 1) vv += __shfl_xor_sync(0xffffffffu, vv, o);
    if ((tid & 31) == 0) red[tid >> 5] = vv;
    __syncthreads();
    if (tid < 8) {
        vv = red[tid];
#pragma unroll
        for (int o = 4; o; o >>= 1) vv += __shfl_xor_sync(0xffu, vv, o);
        if (tid == 0) s_stat[1] = rsqrtf(vv * (1.0f / DMODEL) + LN_EPS);
    }
    __syncthreads();
    float inv = s_stat[1];
    h[base + tid]       = tf32r(d0 * inv * g[tid]       + bb[tid]);
    h[base + tid + 256] = tf32r(d1 * inv * g[tid + 256] + bb[tid + 256]);
}

/* ---------------- host driver ---------------- */
extern "C" void kernel_launch(void* const* d_in, const int* in_sizes, int n_in,
                              void* d_out, int out_size) {
    const int*   x    = (const int*)  d_in[0];
    const float* tok  = (const float*)d_in[1];
    const float* pos  = (const float*)d_in[2];
    const float* Wq   = (const float*)d_in[3];
    const float* Wk   = (const float*)d_in[4];
    const float* Wv   = (const float*)d_in[5];
    const float* Wo   = (const float*)d_in[6];
    const float* ln1g = (const float*)d_in[7];
    const float* ln1b = (const float*)d_in[8];
    const float* W1   = (const float*)d_in[9];
    const float* W2   = (const float*)d_in[10];
    const float* ln2g = (const float*)d_in[11];
    const float* ln2b = (const float*)d_in[12];
    const float* Wl   = (const float*)d_in[13];
    float* out = (float*)d_out;

    float *ph, *pq, *pk, *pv, *pa, *pt, *pff, *pw;
    cudaGetSymbolAddress((void**)&ph,  g_h);
    cudaGetSymbolAddress((void**)&pq,  g_q);
    cudaGetSymbolAddress((void**)&pk,  g_k);
    cudaGetSymbolAddress((void**)&pv,  g_v);
    cudaGetSymbolAddress((void**)&pa,  g_a);
    cudaGetSymbolAddress((void**)&pt,  g_t);
    cudaGetSymbolAddress((void**)&pff, g_ff);
    cudaGetSymbolAddress((void**)&pw,  g_w);

    cudaFuncSetAttribute(attn_tc,    cudaFuncAttributeMaxDynamicSharedMemorySize, ATTN_SMEM);
    cudaFuncSetAttribute(gemm_tc<0>, cudaFuncAttributeMaxDynamicSharedMemorySize, G_SMEM);
    cudaFuncSetAttribute(gemm_tc<1>, cudaFuncAttributeMaxDynamicSharedMemorySize, G_SMEM);
    cudaFuncSetAttribute(gemm_qkv,   cudaFuncAttributeMaxDynamicSharedMemorySize, G_SMEM);

    /* pre-round all weights to tf32 */
    round_copy<<<(6*DMODEL*DMODEL)/256,   256>>>(Wq, pw + WOFF_Q, 6*DMODEL*DMODEL);
    round_copy<<<(6*DMODEL*DMODEL)/256,   256>>>(Wk, pw + WOFF_K, 6*DMODEL*DMODEL);
    round_copy<<<(6*DMODEL*DMODEL)/256,   256>>>(Wv, pw + WOFF_V, 6*DMODEL*DMODEL);
    round_copy<<<(6*DMODEL*DMODEL)/256,   256>>>(Wo, pw + WOFF_O, 6*DMODEL*DMODEL);
    round_copy<<<(6*DMODEL*DFFN)/256,     256>>>(W1, pw + WOFF_1, 6*DMODEL*DFFN);
    round_copy<<<(6*DMODEL*DFFN)/256,     256>>>(W2, pw + WOFF_2, 6*DMODEL*DFFN);
    round_copy<<<(DMODEL*VOCAB)/256,      256>>>(Wl, pw + WOFF_L, DMODEL*VOCAB);

    embed_kernel<<<MROWS * DMODEL / 256, 256>>>(x, tok, pos, ph);

    for (int i = 0; i < NDEPTH; i++) {
        const float* wq = pw + WOFF_Q + (size_t)i * DMODEL * DMODEL;
        const float* wk = pw + WOFF_K + (size_t)i * DMODEL * DMODEL;
        const float* wv = pw + WOFF_V + (size_t)i * DMODEL * DMODEL;
        const float* wo = pw + WOFF_O + (size_t)i * DMODEL * DMODEL;
        const float* w1 = pw + WOFF_1 + (size_t)i * DMODEL * DFFN;
        const float* w2 = pw + WOFF_2 + (size_t)i * DFFN * DMODEL;

        gemm_qkv<<<dim3(DMODEL / 128, MROWS / 128, 3), 256, G_SMEM>>>(
            ph, wq, wk, wv, pq, pk, pv, DMODEL, DMODEL);

        l2norm_kernel<<<(2 * MROWS * NHEADS) / 8, 256>>>(pq, pk);

        attn_tc<<<dim3(SEQ / 64, NHEADS, NB), 128, ATTN_SMEM>>>(pq, pk, pv, pa);

        gemm_tc<0><<<dim3(DMODEL / 128, MROWS / 128), 256, G_SMEM>>>(pa, wo, pt, DMODEL, DMODEL);
        ln_res_kernel<<<MROWS, 256>>>(ph, pt, ln1g + i * DMODEL, ln1b + i * DMODEL);

        gemm_tc<1><<<dim3(DFFN / 128, MROWS / 128), 256, G_SMEM>>>(ph, w1, pff, DFFN, DMODEL);
        gemm_tc<0><<<dim3(DMODEL / 128, MROWS / 128), 256, G_SMEM>>>(pff, w2, pt, DMODEL, DFFN);
        ln_res_kernel<<<MROWS, 256>>>(ph, pt, ln2g + i * DMODEL, ln2b + i * DMODEL);
    }

    gemm_tc<0><<<dim3(VOCAB / 128, MROWS / 128), 256, G_SMEM>>>(ph, pw + WOFF_L, out, VOCAB, DMODEL);
}

// round 6
// speedup vs baseline: 3.5965x; 1.0440x over previous
#include <cuda_runtime.h>
#include <cuda_bf16.h>
#include <math.h>
#include <stdint.h>

#define NB      2
#define SEQ     2048
#define DMODEL  512
#define VOCAB   32000
#define NHEADS  8
#define DHEAD   64
#define DFFN    2048
#define NDEPTH  6
#define MROWS   (NB*SEQ)   /* 4096 */

#define RES_SCALE 1.86120971820393f
#define ATTN_SCALE 8.0f
#define LN_EPS 1e-5f

/* ---------------- scratch ---------------- */
__device__ float g_h [MROWS*DMODEL];   /* fp32 residual stream */
__device__ float g_hr[MROWS*DMODEL];   /* tf32-rounded GEMM input copy */
__device__ float g_q [MROWS*DMODEL];
__device__ float g_k [MROWS*DMODEL];
__device__ float g_v [MROWS*DMODEL];
__device__ float g_a [MROWS*DMODEL];
__device__ float g_t [MROWS*DMODEL];
__device__ float g_ff[MROWS*DFFN];
#define WOFF_Q  0
#define WOFF_K  1572864
#define WOFF_V  3145728
#define WOFF_O  4718592
#define WOFF_1  6291456
#define WOFF_2  12582912
#define WOFF_L  18874368
#define WTOTAL  35258368
__device__ float g_w[WTOTAL];

__device__ __forceinline__ float tf32r(float x) {
    unsigned u;
    asm("cvt.rna.tf32.f32 %0, %1;" : "=r"(u) : "f"(x));
    return __uint_as_float(u);
}
__device__ __forceinline__ uint32_t smem_u32(const void* p) {
    uint32_t a;
    asm("{ .reg .u64 t; cvta.to.shared.u64 t, %1; cvt.u32.u64 %0, t; }" : "=r"(a) : "l"(p));
    return a;
}
__device__ __forceinline__ void cpa16(uint32_t dst, const void* src) {
    asm volatile("cp.async.cg.shared.global [%0], [%1], 16;" :: "r"(dst), "l"(src));
}
__device__ __forceinline__ void mma_tf32(float* d, const unsigned* a, unsigned b0, unsigned b1) {
    asm volatile(
        "mma.sync.aligned.m16n8k8.row.col.f32.tf32.tf32.f32 "
        "{%0,%1,%2,%3},{%4,%5,%6,%7},{%8,%9},{%0,%1,%2,%3};"
        : "+f"(d[0]), "+f"(d[1]), "+f"(d[2]), "+f"(d[3])
        : "r"(a[0]), "r"(a[1]), "r"(a[2]), "r"(a[3]), "r"(b0), "r"(b1));
}

/* ---------------- weight pre-round (vectorized) ---------------- */
__global__ void round_copy4(const float4* __restrict__ src, float4* __restrict__ dst, int n4) {
    int i = blockIdx.x * 256 + threadIdx.x;
    if (i < n4) {
        float4 v = src[i];
        v.x = tf32r(v.x); v.y = tf32r(v.y); v.z = tf32r(v.z); v.w = tf32r(v.w);
        dst[i] = v;
    }
}

/* ---------------- embedding: dual output ---------------- */
__global__ void embed_kernel(const int* __restrict__ x, const float* __restrict__ tok,
                             const float* __restrict__ pos, float* __restrict__ h,
                             float* __restrict__ hr) {
    int idx = blockIdx.x * 256 + threadIdx.x;
    int row = idx >> 9;
    int d   = idx & 511;
    int n   = row & (SEQ - 1);
    float v = tok[x[row] * DMODEL + d] + pos[n * DMODEL + d];
    h[idx]  = v;
    hr[idx] = tf32r(v);
}

/* ================= TF32 mma.sync GEMM, cp.async 3-stage =================
   EPI: 0 = plain, 1 = exact GELU + tf32 round, 2 = per-head L2-normalize
        (rows x 64-col head segments; requires N==512, head-aligned tiles)
        + tf32 round, 3 = plain + tf32 round. */
#define AST     36
#define ASTAGE  (128*AST)
#define BSTAGE  (32*128)
#define STAGE_F (ASTAGE+BSTAGE)
#define G_SMEM  (3*STAGE_F*4)

template<int EPI>
__device__ __forceinline__ void gemm_body(const float* __restrict__ A,
                                          const float* __restrict__ B,
                                          float* __restrict__ C,
                                          int N, int K, float* sm) {
    int tid = threadIdx.x;
    int warp = tid >> 5, lane = tid & 31;
    int wm = warp >> 1, wn = warp & 1;
    int g = lane >> 2, tg = lane & 3;
    int bm = blockIdx.y * 128, bn = blockIdx.x * 128;

    uint32_t sb = smem_u32(sm);

    float acc[2][8][4];
#pragma unroll
    for (int i = 0; i < 2; i++)
#pragma unroll
        for (int j = 0; j < 8; j++)
#pragma unroll
            for (int t = 0; t < 4; t++) acc[i][j][t] = 0.0f;

    int nIter = K >> 5;

#define STAGE(slot, k0)                                                          \
    do {                                                                         \
        uint32_t as_ = sb + (uint32_t)(slot) * (STAGE_F * 4);                    \
        uint32_t bs_ = as_ + ASTAGE * 4;                                         \
        _Pragma("unroll")                                                        \
        for (int it_ = 0; it_ < 4; it_++) {                                      \
            int id_ = tid + it_ * 256;                                           \
            int r_ = id_ >> 3, c4_ = (id_ & 7) * 4;                              \
            cpa16(as_ + (r_ * AST + c4_) * 4,                                    \
                  A + (size_t)(bm + r_) * K + (k0) + c4_);                       \
        }                                                                        \
        _Pragma("unroll")                                                        \
        for (int it_ = 0; it_ < 4; it_++) {                                      \
            int id_ = tid + it_ * 256;                                           \
            int r_ = id_ >> 5, cn_ = id_ & 31;                                   \
            int pc_ = cn_ ^ ((r_ & 3) << 1);                                     \
            cpa16(bs_ + (r_ * 128 + pc_ * 4) * 4,                                \
                  B + (size_t)((k0) + r_) * N + bn + cn_ * 4);                   \
        }                                                                        \
        asm volatile("cp.async.commit_group;" ::: "memory");                     \
    } while (0)

    STAGE(0, 0);
    if (nIter > 1) STAGE(1, 32);
    else asm volatile("cp.async.commit_group;" ::: "memory");

    for (int it = 0; it < nIter; it++) {
        asm volatile("cp.async.wait_group 1;" ::: "memory");
        __syncthreads();

        int slot = it % 3;
        const float* as = sm + slot * STAGE_F;
        const float* bs = as + ASTAGE;

#pragma unroll
        for (int ks = 0; ks < 4; ks++) {
            int k8 = ks * 8;
            unsigned af[2][4];
#pragma unroll
            for (int i = 0; i < 2; i++) {
                int mr = wm * 32 + i * 16 + g;
                af[i][0] = __float_as_uint(as[mr * AST + k8 + tg]);
                af[i][1] = __float_as_uint(as[(mr + 8) * AST + k8 + tg]);
                af[i][2] = __float_as_uint(as[mr * AST + k8 + tg + 4]);
                af[i][3] = __float_as_uint(as[(mr + 8) * AST + k8 + tg + 4]);
            }
#pragma unroll
            for (int j = 0; j < 8; j++) {
                int nc = wn * 64 + j * 8 + g;
                int phys = ((nc >> 2) ^ (tg << 1)) * 4 + (nc & 3);
                unsigned b0 = __float_as_uint(bs[(k8 + tg) * 128 + phys]);
                unsigned b1 = __float_as_uint(bs[(k8 + tg + 4) * 128 + phys]);
                mma_tf32(acc[0][j], af[0], b0, b1);
                mma_tf32(acc[1][j], af[1], b0, b1);
            }
        }
        __syncthreads();
        if (it + 2 < nIter) STAGE((it + 2) % 3, (it + 2) * 32);
        else asm volatile("cp.async.commit_group;" ::: "memory");
    }
#undef STAGE

    /* EPI==2: per-row-half L2 norm over this warp's 64-col head segment */
    float inv0[2] = {1.0f, 1.0f};
    if (EPI == 2) {
#pragma unroll
        for (int i = 0; i < 2; i++) {
            float ss0 = 0.0f, ss1 = 0.0f;
#pragma unroll
            for (int j = 0; j < 8; j++) {
                ss0 += acc[i][j][0] * acc[i][j][0] + acc[i][j][1] * acc[i][j][1];
                ss1 += acc[i][j][2] * acc[i][j][2] + acc[i][j][3] * acc[i][j][3];
            }
            ss0 += __shfl_xor_sync(0xffffffffu, ss0, 1);
            ss0 += __shfl_xor_sync(0xffffffffu, ss0, 2);
            ss1 += __shfl_xor_sync(0xffffffffu, ss1, 1);
            ss1 += __shfl_xor_sync(0xffffffffu, ss1, 2);
            float n0 = 1.0f / fmaxf(sqrtf(ss0), 1e-12f);
            float n1 = 1.0f / fmaxf(sqrtf(ss1), 1e-12f);
            /* apply row-half 0 scale to t0/t1, row-half 1 scale to t2/t3 */
#pragma unroll
            for (int j = 0; j < 8; j++) {
                acc[i][j][0] *= n0; acc[i][j][1] *= n0;
                acc[i][j][2] *= n1; acc[i][j][3] *= n1;
            }
        }
    }

#pragma unroll
    for (int i = 0; i < 2; i++) {
        int r0 = bm + wm * 32 + i * 16 + g;
#pragma unroll
        for (int j = 0; j < 8; j++) {
            int col = bn + wn * 64 + j * 8 + tg * 2;
            float v0 = acc[i][j][0], v1 = acc[i][j][1];
            float v2 = acc[i][j][2], v3 = acc[i][j][3];
            if (EPI == 1) {
                v0 = tf32r(0.5f * v0 * (1.0f + erff(v0 * 0.70710678118654752f)));
                v1 = tf32r(0.5f * v1 * (1.0f + erff(v1 * 0.70710678118654752f)));
                v2 = tf32r(0.5f * v2 * (1.0f + erff(v2 * 0.70710678118654752f)));
                v3 = tf32r(0.5f * v3 * (1.0f + erff(v3 * 0.70710678118654752f)));
            } else if (EPI == 2 || EPI == 3) {
                v0 = tf32r(v0); v1 = tf32r(v1); v2 = tf32r(v2); v3 = tf32r(v3);
            }
            *(float2*)&C[(size_t)r0 * N + col]       = make_float2(v0, v1);
            *(float2*)&C[(size_t)(r0 + 8) * N + col] = make_float2(v2, v3);
        }
    }
}

template<int EPI>
__global__ __launch_bounds__(256) void gemm_tc(const float* __restrict__ A,
                                               const float* __restrict__ B,
                                               float* __restrict__ C, int N, int K) {
    extern __shared__ float sm[];
    gemm_body<EPI>(A, B, C, N, K, sm);
}

/* QKV: z=0 (Q) and z=1 (K) get l2norm epilogue; z=2 (V) plain+round */
__global__ __launch_bounds__(256) void gemm_qkv(const float* __restrict__ A,
                                                const float* __restrict__ B0,
                                                const float* __restrict__ B1,
                                                const float* __restrict__ B2,
                                                float* __restrict__ C0,
                                                float* __restrict__ C1,
                                                float* __restrict__ C2,
                                                int N, int K) {
    extern __shared__ float sm[];
    if (blockIdx.z == 0)      gemm_body<2>(A, B0, C0, N, K, sm);
    else if (blockIdx.z == 1) gemm_body<2>(A, B1, C1, N, K, sm);
    else                      gemm_body<3>(A, B2, C2, N, K, sm);
}

/* ================= TF32 flash attention (R3 core, unchanged) ============= */
#define APAD 72
#define ATTN_SMEM (3 * 64 * APAD * 4)

__global__ __launch_bounds__(128) void attn_tc(const float* __restrict__ q,
                                               const float* __restrict__ k,
                                               const float* __restrict__ v,
                                               float* __restrict__ o) {
    extern __shared__ float sm[];
    float* Ks = sm;
    float* Vs = sm + 64 * APAD;
    float* Ps = sm + 2 * 64 * APAD;

    int qt = gridDim.x - 1 - blockIdx.x;
    int hh = blockIdx.y, b = blockIdx.z;
    int tid = threadIdx.x, warp = tid >> 5, lane = tid & 31;
    int g = lane >> 2, tg = lane & 3;

    unsigned qf[8][4];
    const float* qbase = q + (size_t)(b * SEQ + qt * 64 + warp * 16 + g) * DMODEL + hh * 64;
#pragma unroll
    for (int kk = 0; kk < 8; kk++) {
        qf[kk][0] = __float_as_uint(qbase[kk * 8 + tg]);
        qf[kk][1] = __float_as_uint(qbase[(size_t)8 * DMODEL + kk * 8 + tg]);
        qf[kk][2] = __float_as_uint(qbase[kk * 8 + tg + 4]);
        qf[kk][3] = __float_as_uint(qbase[(size_t)8 * DMODEL + kk * 8 + tg + 4]);
    }

    float oa[8][4];
#pragma unroll
    for (int j = 0; j < 8; j++)
#pragma unroll
        for (int t = 0; t < 4; t++) oa[j][t] = 0.0f;
    float m0 = -1e30f, m1 = -1e30f, l0 = 0.0f, l1 = 0.0f;

    int prow0 = (warp * 16 + g) * APAD;
    int prow1 = (warp * 16 + g + 8) * APAD;

    for (int kt = 0; kt <= qt; kt++) {
        __syncthreads();
        for (int i = tid; i < 1024; i += 128) {
            int r  = i >> 4;
            int c4 = (i & 15) * 4;
            size_t gg = (size_t)(b * SEQ + kt * 64 + r) * DMODEL + hh * 64 + c4;
            float4 k4 = *(const float4*)(k + gg);
            int rk = r ^ ((c4 >> 2) & 7);
            Ks[(c4 + 0) * APAD + rk] = k4.x;
            Ks[(c4 + 1) * APAD + rk] = k4.y;
            Ks[(c4 + 2) * APAD + rk] = k4.z;
            Ks[(c4 + 3) * APAD + rk] = k4.w;
            float4 v4 = *(const float4*)(v + gg);
            Vs[r * APAD + c4 + 0] = v4.x;
            Vs[r * APAD + c4 + 1] = v4.y;
            Vs[r * APAD + c4 + 2] = v4.z;
            Vs[r * APAD + c4 + 3] = v4.w;
        }
        __syncthreads();

        float s[8][4];
#pragma unroll
        for (int j = 0; j < 8; j++)
#pragma unroll
            for (int t = 0; t < 4; t++) s[j][t] = 0.0f;
#pragma unroll
        for (int kk = 0; kk < 8; kk++) {
            int d0 = kk * 8 + tg, d1 = d0 + 4;
            int sw0 = (d0 >> 2) & 7, sw1 = (d1 >> 2) & 7;
#pragma unroll
            for (int j = 0; j < 8; j++) {
                unsigned b0 = __float_as_uint(Ks[d0 * APAD + ((j * 8 + g) ^ sw0)]);
                unsigned b1 = __float_as_uint(Ks[d1 * APAD + ((j * 8 + g) ^ sw1)]);
                mma_tf32(s[j], qf[kk], b0, b1);
            }
        }

        if (kt == qt) {
            int r0 = warp * 16 + g, r1 = r0 + 8;
#pragma unroll
            for (int j = 0; j < 8; j++) {
                int c0 = j * 8 + tg * 2, c1 = c0 + 1;
                s[j][0] = (c0 > r0) ? -1e30f : s[j][0] * ATTN_SCALE;
                s[j][1] = (c1 > r0) ? -1e30f : s[j][1] * ATTN_SCALE;
                s[j][2] = (c0 > r1) ? -1e30f : s[j][2] * ATTN_SCALE;
                s[j][3] = (c1 > r1) ? -1e30f : s[j][3] * ATTN_SCALE;
            }
        } else {
#pragma unroll
            for (int j = 0; j < 8; j++)
#pragma unroll
                for (int t = 0; t < 4; t++) s[j][t] *= ATTN_SCALE;
        }

        float rx0 = -1e30f, rx1 = -1e30f;
#pragma unroll
        for (int j = 0; j < 8; j++) {
            rx0 = fmaxf(rx0, fmaxf(s[j][0], s[j][1]));
            rx1 = fmaxf(rx1, fmaxf(s[j][2], s[j][3]));
        }
        rx0 = fmaxf(rx0, __shfl_xor_sync(0xffffffffu, rx0, 1));
        rx0 = fmaxf(rx0, __shfl_xor_sync(0xffffffffu, rx0, 2));
        rx1 = fmaxf(rx1, __shfl_xor_sync(0xffffffffu, rx1, 1));
        rx1 = fmaxf(rx1, __shfl_xor_sync(0xffffffffu, rx1, 2));

        float mn0 = fmaxf(m0, rx0), mn1 = fmaxf(m1, rx1);
        float cr0 = __expf(m0 - mn0), cr1 = __expf(m1 - mn1);

        float sum0 = 0.0f, sum1 = 0.0f;
#pragma unroll
        for (int j = 0; j < 8; j++) {
            int c0 = j * 8 + tg * 2;
            float e0 = __expf(s[j][0] - mn0);
            float e1 = __expf(s[j][1] - mn0);
            float e2 = __expf(s[j][2] - mn1);
            float e3 = __expf(s[j][3] - mn1);
            sum0 += e0 + e1;
            sum1 += e2 + e3;
            *(float2*)&Ps[prow0 + c0] = make_float2(e0, e1);
            *(float2*)&Ps[prow1 + c0] = make_float2(e2, e3);
        }
        sum0 += __shfl_xor_sync(0xffffffffu, sum0, 1);
        sum0 += __shfl_xor_sync(0xffffffffu, sum0, 2);
        sum1 += __shfl_xor_sync(0xffffffffu, sum1, 1);
        sum1 += __shfl_xor_sync(0xffffffffu, sum1, 2);

        m0 = mn0; m1 = mn1;
        l0 = l0 * cr0 + sum0;
        l1 = l1 * cr1 + sum1;

#pragma unroll
        for (int j = 0; j < 8; j++) {
            oa[j][0] *= cr0; oa[j][1] *= cr0;
            oa[j][2] *= cr1; oa[j][3] *= cr1;
        }
        __syncwarp();

#pragma unroll
        for (int kk = 0; kk < 8; kk++) {
            unsigned a[4];
            a[0] = __float_as_uint(Ps[prow0 + kk * 8 + tg]);
            a[1] = __float_as_uint(Ps[prow1 + kk * 8 + tg]);
            a[2] = __float_as_uint(Ps[prow0 + kk * 8 + tg + 4]);
            a[3] = __float_as_uint(Ps[prow1 + kk * 8 + tg + 4]);
#pragma unroll
            for (int j = 0; j < 8; j++) {
                unsigned b0 = __float_as_uint(Vs[(kk * 8 + tg)     * APAD + j * 8 + g]);
                unsigned b1 = __float_as_uint(Vs[(kk * 8 + tg + 4) * APAD + j * 8 + g]);
                mma_tf32(oa[j], a, b0, b1);
            }
        }
        __syncwarp();
    }

    float inv0 = 1.0f / l0, inv1 = 1.0f / l1;
    size_t orow0 = (size_t)(b * SEQ + qt * 64 + warp * 16 + g) * DMODEL + hh * 64;
    size_t orow1 = orow0 + (size_t)8 * DMODEL;
#pragma unroll
    for (int j = 0; j < 8; j++) {
        int c0 = j * 8 + tg * 2;
        *(float2*)&o[orow0 + c0] = make_float2(tf32r(oa[j][0] * inv0), tf32r(oa[j][1] * inv0));
        *(float2*)&o[orow1 + c0] = make_float2(tf32r(oa[j][2] * inv1), tf32r(oa[j][3] * inv1));
    }
}

/* ---------------- fused residual + LayerNorm, dual output ---------------- */
__global__ void ln_res_kernel(float* __restrict__ h, const float* __restrict__ a,
                              const float* __restrict__ g, const float* __restrict__ bb,
                              float* __restrict__ hr) {
    __shared__ float red[8];
    __shared__ float s_stat[2];
    int row = blockIdx.x, tid = threadIdx.x;
    size_t base = (size_t)row * DMODEL;
    float x0 = fmaf(RES_SCALE, h[base + tid],       a[base + tid]);
    float x1 = fmaf(RES_SCALE, h[base + tid + 256], a[base + tid + 256]);

    float s = x0 + x1;
#pragma unroll
    for (int o = 16; o; o >>= 1) s += __shfl_xor_sync(0xffffffffu, s, o);
    if ((tid & 31) == 0) red[tid >> 5] = s;
    __syncthreads();
    if (tid < 8) {
        s = red[tid];
#pragma unroll
        for (int o = 4; o; o >>= 1) s += __shfl_xor_sync(0xffu, s, o);
        if (tid == 0) s_stat[0] = s * (1.0f / DMODEL);
    }
    __syncthreads();
    float mean = s_stat[0];
    float d0 = x0 - mean, d1 = x1 - mean;
    float vv = d0 * d0 + d1 * d1;
#pragma unroll
    for (int o = 16; o; o >>= 1) vv += __shfl_xor_sync(0xffffffffu, vv, o);
    if ((tid & 31) == 0) red[tid >> 5] = vv;
    __syncthreads();
    if (tid < 8) {
        vv = red[tid];
#pragma unroll
        for (int o = 4; o; o >>= 1) vv += __shfl_xor_sync(0xffu, vv, o);
        if (tid == 0) s_stat[1] = rsqrtf(vv * (1.0f / DMODEL) + LN_EPS);
    }
    __syncthreads();
    float inv = s_stat[1];
    float y0 = d0 * inv * g[tid]       + bb[tid];
    float y1 = d1 * inv * g[tid + 256] + bb[tid + 256];
    h[base + tid]        = y0;
    h[base + tid + 256]  = y1;
    hr[base + tid]       = tf32r(y0);
    hr[base + tid + 256] = tf32r(y1);
}

/* ---------------- host driver ---------------- */
extern "C" void kernel_launch(void* const* d_in, const int* in_sizes, int n_in,
                              void* d_out, int out_size) {
    const int*   x    = (const int*)  d_in[0];
    const float* tok  = (const float*)d_in[1];
    const float* pos  = (const float*)d_in[2];
    const float* Wq   = (const float*)d_in[3];
    const float* Wk   = (const float*)d_in[4];
    const float* Wv   = (const float*)d_in[5];
    const float* Wo   = (const float*)d_in[6];
    const float* ln1g = (const float*)d_in[7];
    const float* ln1b = (const float*)d_in[8];
    const float* W1   = (const float*)d_in[9];
    const float* W2   = (const float*)d_in[10];
    const float* ln2g = (const float*)d_in[11];
    const float* ln2b = (const float*)d_in[12];
    const float* Wl   = (const float*)d_in[13];
    float* out = (float*)d_out;

    float *ph, *phr, *pq, *pk, *pv, *pa, *pt, *pff, *pw;
    cudaGetSymbolAddress((void**)&ph,  g_h);
    cudaGetSymbolAddress((void**)&phr, g_hr);
    cudaGetSymbolAddress((void**)&pq,  g_q);
    cudaGetSymbolAddress((void**)&pk,  g_k);
    cudaGetSymbolAddress((void**)&pv,  g_v);
    cudaGetSymbolAddress((void**)&pa,  g_a);
    cudaGetSymbolAddress((void**)&pt,  g_t);
    cudaGetSymbolAddress((void**)&pff, g_ff);
    cudaGetSymbolAddress((void**)&pw,  g_w);

    cudaFuncSetAttribute(attn_tc,    cudaFuncAttributeMaxDynamicSharedMemorySize, ATTN_SMEM);
    cudaFuncSetAttribute(gemm_tc<0>, cudaFuncAttributeMaxDynamicSharedMemorySize, G_SMEM);
    cudaFuncSetAttribute(gemm_tc<1>, cudaFuncAttributeMaxDynamicSharedMemorySize, G_SMEM);
    cudaFuncSetAttribute(gemm_qkv,   cudaFuncAttributeMaxDynamicSharedMemorySize, G_SMEM);

    round_copy4<<<(6*DMODEL*DMODEL/4+255)/256, 256>>>((const float4*)Wq, (float4*)(pw + WOFF_Q), 6*DMODEL*DMODEL/4);
    round_copy4<<<(6*DMODEL*DMODEL/4+255)/256, 256>>>((const float4*)Wk, (float4*)(pw + WOFF_K), 6*DMODEL*DMODEL/4);
    round_copy4<<<(6*DMODEL*DMODEL/4+255)/256, 256>>>((const float4*)Wv, (float4*)(pw + WOFF_V), 6*DMODEL*DMODEL/4);
    round_copy4<<<(6*DMODEL*DMODEL/4+255)/256, 256>>>((const float4*)Wo, (float4*)(pw + WOFF_O), 6*DMODEL*DMODEL/4);
    round_copy4<<<(6*DMODEL*DFFN/4+255)/256,   256>>>((const float4*)W1, (float4*)(pw + WOFF_1), 6*DMODEL*DFFN/4);
    round_copy4<<<(6*DMODEL*DFFN/4+255)/256,   256>>>((const float4*)W2, (float4*)(pw + WOFF_2), 6*DMODEL*DFFN/4);
    round_copy4<<<(DMODEL*VOCAB/4+255)/256,    256>>>((const float4*)Wl, (float4*)(pw + WOFF_L), DMODEL*VOCAB/4);

    embed_kernel<<<MROWS * DMODEL / 256, 256>>>(x, tok, pos, ph, phr);

    for (int i = 0; i < NDEPTH; i++) {
        const float* wq = pw + WOFF_Q + (size_t)i * DMODEL * DMODEL;
        const float* wk = pw + WOFF_K + (size_t)i * DMODEL * DMODEL;
        const float* wv = pw + WOFF_V + (size_t)i * DMODEL * DMODEL;
        const float* wo = pw + WOFF_O + (size_t)i * DMODEL * DMODEL;
        const float* w1 = pw + WOFF_1 + (size_t)i * DMODEL * DFFN;
        const float* w2 = pw + WOFF_2 + (size_t)i * DFFN * DMODEL;

        gemm_qkv<<<dim3(DMODEL / 128, MROWS / 128, 3), 256, G_SMEM>>>(
            phr, wq, wk, wv, pq, pk, pv, DMODEL, DMODEL);

        attn_tc<<<dim3(SEQ / 64, NHEADS, NB), 128, ATTN_SMEM>>>(pq, pk, pv, pa);

        gemm_tc<0><<<dim3(DMODEL / 128, MROWS / 128), 256, G_SMEM>>>(pa, wo, pt, DMODEL, DMODEL);
        ln_res_kernel<<<MROWS, 256>>>(ph, pt, ln1g + i * DMODEL, ln1b + i * DMODEL, phr);

        gemm_tc<1><<<dim3(DFFN / 128, MROWS / 128), 256, G_SMEM>>>(phr, w1, pff, DFFN, DMODEL);
        gemm_tc<0><<<dim3(DMODEL / 128, MROWS / 128), 256, G_SMEM>>>(pff, w2, pt, DMODEL, DFFN);
        ln_res_kernel<<<MROWS, 256>>>(ph, pt, ln2g + i * DMODEL, ln2b + i * DMODEL, phr);
    }

    gemm_tc<0><<<dim3(VOCAB / 128, MROWS / 128), 256, G_SMEM>>>(phr, pw + WOFF_L, out, VOCAB, DMODEL);
}

// round 8
// speedup vs baseline: 3.7436x; 1.0409x over previous
#include <cuda_runtime.h>
#include <cuda_bf16.h>
#include <math.h>
#include <stdint.h>

#define NB      2
#define SEQ     2048
#define DMODEL  512
#define VOCAB   32000
#define NHEADS  8
#define DHEAD   64
#define DFFN    2048
#define NDEPTH  6
#define MROWS   (NB*SEQ)   /* 4096 */

#define RES_SCALE 1.86120971820393f
#define ATTN_SCALE 8.0f
#define LN_EPS 1e-5f

/* ---------------- scratch ---------------- */
__device__ float g_h [MROWS*DMODEL];   /* fp32 residual stream */
__device__ float g_hr[MROWS*DMODEL];   /* tf32-rounded GEMM input copy */
__device__ float g_q [MROWS*DMODEL];
__device__ float g_k [MROWS*DMODEL];
__device__ float g_v [MROWS*DMODEL];
__device__ float g_a [MROWS*DMODEL];
__device__ float g_t [MROWS*DMODEL];
__device__ float g_ff[MROWS*DFFN];
#define WOFF_Q  0
#define WOFF_K  1572864
#define WOFF_V  3145728
#define WOFF_O  4718592
#define WOFF_1  6291456
#define WOFF_2  12582912
#define WOFF_L  18874368
#define WTOTAL  35258368
__device__ float g_w[WTOTAL];

__device__ __forceinline__ float tf32r(float x) {
    unsigned u;
    asm("cvt.rna.tf32.f32 %0, %1;" : "=r"(u) : "f"(x));
    return __uint_as_float(u);
}
__device__ __forceinline__ uint32_t smem_u32(const void* p) {
    uint32_t a;
    asm("{ .reg .u64 t; cvta.to.shared.u64 t, %1; cvt.u32.u64 %0, t; }" : "=r"(a) : "l"(p));
    return a;
}
__device__ __forceinline__ void cpa16(uint32_t dst, const void* src) {
    asm volatile("cp.async.cg.shared.global [%0], [%1], 16;" :: "r"(dst), "l"(src));
}
__device__ __forceinline__ void mma_tf32(float* d, const unsigned* a, unsigned b0, unsigned b1) {
    asm volatile(
        "mma.sync.aligned.m16n8k8.row.col.f32.tf32.tf32.f32 "
        "{%0,%1,%2,%3},{%4,%5,%6,%7},{%8,%9},{%0,%1,%2,%3};"
        : "+f"(d[0]), "+f"(d[1]), "+f"(d[2]), "+f"(d[3])
        : "r"(a[0]), "r"(a[1]), "r"(a[2]), "r"(a[3]), "r"(b0), "r"(b1));
}

/* ======== single prep kernel: weight tf32-round + embedding ========
   float4-unit boundaries (cumulative): */
#define PB0  393216u   /* Wq  */
#define PB1  786432u   /* Wk  */
#define PB2  1179648u  /* Wv  */
#define PB3  1572864u  /* Wo  */
#define PB4  3145728u  /* W1  */
#define PB5  4718592u  /* W2  */
#define PB6  8814592u  /* Wl  */
#define PB7  9338880u  /* embed (524288 f4) */
__global__ __launch_bounds__(256) void prep_kernel(
    const int* __restrict__ x, const float* __restrict__ tok, const float* __restrict__ pos,
    const float4* __restrict__ Wq, const float4* __restrict__ Wk, const float4* __restrict__ Wv,
    const float4* __restrict__ Wo, const float4* __restrict__ W1, const float4* __restrict__ W2,
    const float4* __restrict__ Wl, float4* __restrict__ w4,
    float4* __restrict__ h4, float4* __restrict__ hr4) {
    unsigned i = blockIdx.x * 256 + threadIdx.x;
    if (i < PB6) {
        const float4* src;
        unsigned rel, dst;
        if (i < PB3) {
            if (i < PB0)      { src = Wq; rel = i;       dst = i; }
            else if (i < PB1) { src = Wk; rel = i - PB0; dst = i; }
            else if (i < PB2) { src = Wv; rel = i - PB1; dst = i; }
            else              { src = Wo; rel = i - PB2; dst = i; }
        } else if (i < PB4)   { src = W1; rel = i - PB3; dst = i; }
        else if (i < PB5)     { src = W2; rel = i - PB4; dst = i; }
        else                  { src = Wl; rel = i - PB5; dst = i; }
        float4 v = src[rel];
        v.x = tf32r(v.x); v.y = tf32r(v.y); v.z = tf32r(v.z); v.w = tf32r(v.w);
        w4[dst] = v;
    } else {
        unsigned e = i - PB6;             /* f4 index over MROWS*DMODEL/4 */
        int row = e >> 7;                 /* 128 f4 per row */
        int d4  = e & 127;
        int n   = row & (SEQ - 1);
        float4 t = *(const float4*)(tok + (size_t)x[row] * DMODEL + d4 * 4);
        float4 p = *(const float4*)(pos + (size_t)n * DMODEL + d4 * 4);
        float4 v = make_float4(t.x + p.x, t.y + p.y, t.z + p.z, t.w + p.w);
        h4[e] = v;
        v.x = tf32r(v.x); v.y = tf32r(v.y); v.z = tf32r(v.z); v.w = tf32r(v.w);
        hr4[e] = v;
    }
}

/* ================= TF32 mma.sync GEMM, cp.async 3-stage ================= */
#define AST     36
#define ASTAGE  (128*AST)
#define BSTAGE  (32*128)
#define STAGE_F (ASTAGE+BSTAGE)
#define G_SMEM  (3*STAGE_F*4)

template<int EPI>
__device__ __forceinline__ void gemm_body(const float* __restrict__ A,
                                          const float* __restrict__ B,
                                          float* __restrict__ C,
                                          int N, int K, float* sm) {
    int tid = threadIdx.x;
    int warp = tid >> 5, lane = tid & 31;
    int wm = warp >> 1, wn = warp & 1;
    int g = lane >> 2, tg = lane & 3;
    int bm = blockIdx.y * 128, bn = blockIdx.x * 128;

    uint32_t sb = smem_u32(sm);

    float acc[2][8][4];
#pragma unroll
    for (int i = 0; i < 2; i++)
#pragma unroll
        for (int j = 0; j < 8; j++)
#pragma unroll
            for (int t = 0; t < 4; t++) acc[i][j][t] = 0.0f;

    int nIter = K >> 5;

#define STAGE(slot, k0)                                                          \
    do {                                                                         \
        uint32_t as_ = sb + (uint32_t)(slot) * (STAGE_F * 4);                    \
        uint32_t bs_ = as_ + ASTAGE * 4;                                         \
        _Pragma("unroll")                                                        \
        for (int it_ = 0; it_ < 4; it_++) {                                      \
            int id_ = tid + it_ * 256;                                           \
            int r_ = id_ >> 3, c4_ = (id_ & 7) * 4;                              \
            cpa16(as_ + (r_ * AST + c4_) * 4,                                    \
                  A + (size_t)(bm + r_) * K + (k0) + c4_);                       \
        }                                                                        \
        _Pragma("unroll")                                                        \
        for (int it_ = 0; it_ < 4; it_++) {                                      \
            int id_ = tid + it_ * 256;                                           \
            int r_ = id_ >> 5, cn_ = id_ & 31;                                   \
            int pc_ = cn_ ^ ((r_ & 3) << 1);                                     \
            cpa16(bs_ + (r_ * 128 + pc_ * 4) * 4,                                \
                  B + (size_t)((k0) + r_) * N + bn + cn_ * 4);                   \
        }                                                                        \
        asm volatile("cp.async.commit_group;" ::: "memory");                     \
    } while (0)

    STAGE(0, 0);
    if (nIter > 1) STAGE(1, 32);
    else asm volatile("cp.async.commit_group;" ::: "memory");

    for (int it = 0; it < nIter; it++) {
        asm volatile("cp.async.wait_group 1;" ::: "memory");
        __syncthreads();

        int slot = it % 3;
        const float* as = sm + slot * STAGE_F;
        const float* bs = as + ASTAGE;

#pragma unroll
        for (int ks = 0; ks < 4; ks++) {
            int k8 = ks * 8;
            unsigned af[2][4];
#pragma unroll
            for (int i = 0; i < 2; i++) {
                int mr = wm * 32 + i * 16 + g;
                af[i][0] = __float_as_uint(as[mr * AST + k8 + tg]);
                af[i][1] = __float_as_uint(as[(mr + 8) * AST + k8 + tg]);
                af[i][2] = __float_as_uint(as[mr * AST + k8 + tg + 4]);
                af[i][3] = __float_as_uint(as[(mr + 8) * AST + k8 + tg + 4]);
            }
#pragma unroll
            for (int j = 0; j < 8; j++) {
                int nc = wn * 64 + j * 8 + g;
                int phys = ((nc >> 2) ^ (tg << 1)) * 4 + (nc & 3);
                unsigned b0 = __float_as_uint(bs[(k8 + tg) * 128 + phys]);
                unsigned b1 = __float_as_uint(bs[(k8 + tg + 4) * 128 + phys]);
                mma_tf32(acc[0][j], af[0], b0, b1);
                mma_tf32(acc[1][j], af[1], b0, b1);
            }
        }
        __syncthreads();
        if (it + 2 < nIter) STAGE((it + 2) % 3, (it + 2) * 32);
        else asm volatile("cp.async.commit_group;" ::: "memory");
    }
#undef STAGE

    if (EPI == 2) {
#pragma unroll
        for (int i = 0; i < 2; i++) {
            float ss0 = 0.0f, ss1 = 0.0f;
#pragma unroll
            for (int j = 0; j < 8; j++) {
                ss0 += acc[i][j][0] * acc[i][j][0] + acc[i][j][1] * acc[i][j][1];
                ss1 += acc[i][j][2] * acc[i][j][2] + acc[i][j][3] * acc[i][j][3];
            }
            ss0 += __shfl_xor_sync(0xffffffffu, ss0, 1);
            ss0 += __shfl_xor_sync(0xffffffffu, ss0, 2);
            ss1 += __shfl_xor_sync(0xffffffffu, ss1, 1);
            ss1 += __shfl_xor_sync(0xffffffffu, ss1, 2);
            float n0 = 1.0f / fmaxf(sqrtf(ss0), 1e-12f);
            float n1 = 1.0f / fmaxf(sqrtf(ss1), 1e-12f);
#pragma unroll
            for (int j = 0; j < 8; j++) {
                acc[i][j][0] *= n0; acc[i][j][1] *= n0;
                acc[i][j][2] *= n1; acc[i][j][3] *= n1;
            }
        }
    }

#pragma unroll
    for (int i = 0; i < 2; i++) {
        int r0 = bm + wm * 32 + i * 16 + g;
#pragma unroll
        for (int j = 0; j < 8; j++) {
            int col = bn + wn * 64 + j * 8 + tg * 2;
            float v0 = acc[i][j][0], v1 = acc[i][j][1];
            float v2 = acc[i][j][2], v3 = acc[i][j][3];
            if (EPI == 1) {
                v0 = tf32r(0.5f * v0 * (1.0f + erff(v0 * 0.70710678118654752f)));
                v1 = tf32r(0.5f * v1 * (1.0f + erff(v1 * 0.70710678118654752f)));
                v2 = tf32r(0.5f * v2 * (1.0f + erff(v2 * 0.70710678118654752f)));
                v3 = tf32r(0.5f * v3 * (1.0f + erff(v3 * 0.70710678118654752f)));
            } else if (EPI == 2 || EPI == 3) {
                v0 = tf32r(v0); v1 = tf32r(v1); v2 = tf32r(v2); v3 = tf32r(v3);
            }
            *(float2*)&C[(size_t)r0 * N + col]       = make_float2(v0, v1);
            *(float2*)&C[(size_t)(r0 + 8) * N + col] = make_float2(v2, v3);
        }
    }
}

template<int EPI>
__global__ __launch_bounds__(256) void gemm_tc(const float* __restrict__ A,
                                               const float* __restrict__ B,
                                               float* __restrict__ C, int N, int K) {
    extern __shared__ float sm[];
    gemm_body<EPI>(A, B, C, N, K, sm);
}

__global__ __launch_bounds__(256) void gemm_qkv(const float* __restrict__ A,
                                                const float* __restrict__ B0,
                                                const float* __restrict__ B1,
                                                const float* __restrict__ B2,
                                                float* __restrict__ C0,
                                                float* __restrict__ C1,
                                                float* __restrict__ C2,
                                                int N, int K) {
    extern __shared__ float sm[];
    if (blockIdx.z == 0)      gemm_body<2>(A, B0, C0, N, K, sm);
    else if (blockIdx.z == 1) gemm_body<2>(A, B1, C1, N, K, sm);
    else                      gemm_body<3>(A, B2, C2, N, K, sm);
}

/* ================= TF32 flash attention, cp.async double-buffered =========
   Ks: row-major [key][d] pad 68 (banks 4g+tg distinct).
   Vs: row-major [key][d] pad 72 (banks 8tg+g distinct).
   Ps: [row][72] per-warp P round-trip. */
#define KPAD 68
#define VPAD 72
#define KS_F (64*KPAD)
#define VS_F (64*VPAD)
#define ATTN_SMEM ((2*KS_F + 2*VS_F + 64*72) * 4)

__global__ __launch_bounds__(128) void attn_tc(const float* __restrict__ q,
                                               const float* __restrict__ k,
                                               const float* __restrict__ v,
                                               float* __restrict__ o) {
    extern __shared__ float sm[];
    float* Ks0 = sm;
    float* Vs0 = sm + 2 * KS_F;
    float* Ps  = sm + 2 * KS_F + 2 * VS_F;
    uint32_t sb = smem_u32(sm);

    int qt = gridDim.x - 1 - blockIdx.x;
    int hh = blockIdx.y, b = blockIdx.z;
    int tid = threadIdx.x, warp = tid >> 5, lane = tid & 31;
    int g = lane >> 2, tg = lane & 3;

    unsigned qf[8][4];
    const float* qbase = q + (size_t)(b * SEQ + qt * 64 + warp * 16 + g) * DMODEL + hh * 64;
#pragma unroll
    for (int kk = 0; kk < 8; kk++) {
        qf[kk][0] = __float_as_uint(qbase[kk * 8 + tg]);
        qf[kk][1] = __float_as_uint(qbase[(size_t)8 * DMODEL + kk * 8 + tg]);
        qf[kk][2] = __float_as_uint(qbase[kk * 8 + tg + 4]);
        qf[kk][3] = __float_as_uint(qbase[(size_t)8 * DMODEL + kk * 8 + tg + 4]);
    }

    float oa[8][4];
#pragma unroll
    for (int j = 0; j < 8; j++)
#pragma unroll
        for (int t = 0; t < 4; t++) oa[j][t] = 0.0f;
    float m0 = -1e30f, m1 = -1e30f, l0 = 0.0f, l1 = 0.0f;

    int prow0 = (warp * 16 + g) * 72;
    int prow1 = (warp * 16 + g + 8) * 72;

    /* stage tile kt into buffer bb via cp.async (no commit here) */
#define ASTAGE_TILE(kt_, bb_)                                                    \
    do {                                                                         \
        uint32_t ka_ = sb + (uint32_t)(bb_) * (KS_F * 4);                        \
        uint32_t va_ = sb + (2 * KS_F + (bb_) * VS_F) * 4;                       \
        _Pragma("unroll")                                                        \
        for (int it_ = 0; it_ < 8; it_++) {                                      \
            int i_ = tid + it_ * 128;                                            \
            int r_ = i_ >> 4, c4_ = (i_ & 15) * 4;                               \
            size_t gg_ = (size_t)(b * SEQ + (kt_) * 64 + r_) * DMODEL + hh * 64 + c4_; \
            cpa16(ka_ + (r_ * KPAD + c4_) * 4, k + gg_);                         \
            cpa16(va_ + (r_ * VPAD + c4_) * 4, v + gg_);                         \
        }                                                                        \
        asm volatile("cp.async.commit_group;" ::: "memory");                     \
    } while (0)

    ASTAGE_TILE(0, 0);

    for (int kt = 0; kt <= qt; kt++) {
        int bb = kt & 1;
        if (kt < qt) {
            ASTAGE_TILE(kt + 1, bb ^ 1);
            asm volatile("cp.async.wait_group 1;" ::: "memory");
        } else {
            asm volatile("cp.async.wait_group 0;" ::: "memory");
        }
        __syncthreads();

        const float* Ks = Ks0 + bb * KS_F;
        const float* Vs = Vs0 + bb * VS_F;

        float s[8][4];
#pragma unroll
        for (int j = 0; j < 8; j++)
#pragma unroll
            for (int t = 0; t < 4; t++) s[j][t] = 0.0f;
#pragma unroll
        for (int kk = 0; kk < 8; kk++) {
            int d0 = kk * 8 + tg, d1 = d0 + 4;
#pragma unroll
            for (int j = 0; j < 8; j++) {
                const float* krow = Ks + (j * 8 + g) * KPAD;
                unsigned b0 = __float_as_uint(krow[d0]);
                unsigned b1 = __float_as_uint(krow[d1]);
                mma_tf32(s[j], qf[kk], b0, b1);
            }
        }

        if (kt == qt) {
            int r0 = warp * 16 + g, r1 = r0 + 8;
#pragma unroll
            for (int j = 0; j < 8; j++) {
                int c0 = j * 8 + tg * 2, c1 = c0 + 1;
                s[j][0] = (c0 > r0) ? -1e30f : s[j][0] * ATTN_SCALE;
                s[j][1] = (c1 > r0) ? -1e30f : s[j][1] * ATTN_SCALE;
                s[j][2] = (c0 > r1) ? -1e30f : s[j][2] * ATTN_SCALE;
                s[j][3] = (c1 > r1) ? -1e30f : s[j][3] * ATTN_SCALE;
            }
        } else {
#pragma unroll
            for (int j = 0; j < 8; j++)
#pragma unroll
                for (int t = 0; t < 4; t++) s[j][t] *= ATTN_SCALE;
        }

        float rx0 = -1e30f, rx1 = -1e30f;
#pragma unroll
        for (int j = 0; j < 8; j++) {
            rx0 = fmaxf(rx0, fmaxf(s[j][0], s[j][1]));
            rx1 = fmaxf(rx1, fmaxf(s[j][2], s[j][3]));
        }
        rx0 = fmaxf(rx0, __shfl_xor_sync(0xffffffffu, rx0, 1));
        rx0 = fmaxf(rx0, __shfl_xor_sync(0xffffffffu, rx0, 2));
        rx1 = fmaxf(rx1, __shfl_xor_sync(0xffffffffu, rx1, 1));
        rx1 = fmaxf(rx1, __shfl_xor_sync(0xffffffffu, rx1, 2));

        float mn0 = fmaxf(m0, rx0), mn1 = fmaxf(m1, rx1);
        float cr0 = __expf(m0 - mn0), cr1 = __expf(m1 - mn1);

        float sum0 = 0.0f, sum1 = 0.0f;
#pragma unroll
        for (int j = 0; j < 8; j++) {
            int c0 = j * 8 + tg * 2;
            float e0 = __expf(s[j][0] - mn0);
            float e1 = __expf(s[j][1] - mn0);
            float e2 = __expf(s[j][2] - mn1);
            float e3 = __expf(s[j][3] - mn1);
            sum0 += e0 + e1;
            sum1 += e2 + e3;
            *(float2*)&Ps[prow0 + c0] = make_float2(e0, e1);
            *(float2*)&Ps[prow1 + c0] = make_float2(e2, e3);
        }
        sum0 += __shfl_xor_sync(0xffffffffu, sum0, 1);
        sum0 += __shfl_xor_sync(0xffffffffu, sum0, 2);
        sum1 += __shfl_xor_sync(0xffffffffu, sum1, 1);
        sum1 += __shfl_xor_sync(0xffffffffu, sum1, 2);

        m0 = mn0; m1 = mn1;
        l0 = l0 * cr0 + sum0;
        l1 = l1 * cr1 + sum1;

#pragma unroll
        for (int j = 0; j < 8; j++) {
            oa[j][0] *= cr0; oa[j][1] *= cr0;
            oa[j][2] *= cr1; oa[j][3] *= cr1;
        }
        __syncwarp();

#pragma unroll
        for (int kk = 0; kk < 8; kk++) {
            unsigned a[4];
            a[0] = __float_as_uint(Ps[prow0 + kk * 8 + tg]);
            a[1] = __float_as_uint(Ps[prow1 + kk * 8 + tg]);
            a[2] = __float_as_uint(Ps[prow0 + kk * 8 + tg + 4]);
            a[3] = __float_as_uint(Ps[prow1 + kk * 8 + tg + 4]);
#pragma unroll
            for (int j = 0; j < 8; j++) {
                unsigned b0 = __float_as_uint(Vs[(kk * 8 + tg)     * VPAD + j * 8 + g]);
                unsigned b1 = __float_as_uint(Vs[(kk * 8 + tg + 4) * VPAD + j * 8 + g]);
                mma_tf32(oa[j], a, b0, b1);
            }
        }
        __syncthreads();
    }
#undef ASTAGE_TILE

    float inv0 = 1.0f / l0, inv1 = 1.0f / l1;
    size_t orow0 = (size_t)(b * SEQ + qt * 64 + warp * 16 + g) * DMODEL + hh * 64;
    size_t orow1 = orow0 + (size_t)8 * DMODEL;
#pragma unroll
    for (int j = 0; j < 8; j++) {
        int c0 = j * 8 + tg * 2;
        *(float2*)&o[orow0 + c0] = make_float2(tf32r(oa[j][0] * inv0), tf32r(oa[j][1] * inv0));
        *(float2*)&o[orow1 + c0] = make_float2(tf32r(oa[j][2] * inv1), tf32r(oa[j][3] * inv1));
    }
}

/* ---------------- fused residual + LayerNorm, dual output ---------------- */
__global__ void ln_res_kernel(float* __restrict__ h, const float* __restrict__ a,
                              const float* __restrict__ g, const float* __restrict__ bb,
                              float* __restrict__ hr) {
    __shared__ float red[8];
    __shared__ float s_stat[2];
    int row = blockIdx.x, tid = threadIdx.x;
    size_t base = (size_t)row * DMODEL;
    float x0 = fmaf(RES_SCALE, h[base + tid],       a[base + tid]);
    float x1 = fmaf(RES_SCALE, h[base + tid + 256], a[base + tid + 256]);

    float s = x0 + x1;
#pragma unroll
    for (int o = 16; o; o >>= 1) s += __shfl_xor_sync(0xffffffffu, s, o);
    if ((tid & 31) == 0) red[tid >> 5] = s;
    __syncthreads();
    if (tid < 8) {
        s = red[tid];
#pragma unroll
        for (int o = 4; o; o >>= 1) s += __shfl_xor_sync(0xffu, s, o);
        if (tid == 0) s_stat[0] = s * (1.0f / DMODEL);
    }
    __syncthreads();
    float mean = s_stat[0];
    float d0 = x0 - mean, d1 = x1 - mean;
    float vv = d0 * d0 + d1 * d1;
#pragma unroll
    for (int o = 16; o; o >>= 1) vv += __shfl_xor_sync(0xffffffffu, vv, o);
    if ((tid & 31) == 0) red[tid >> 5] = vv;
    __syncthreads();
    if (tid < 8) {
        vv = red[tid];
#pragma unroll
        for (int o = 4; o; o >>= 1) vv += __shfl_xor_sync(0xffu, vv, o);
        if (tid == 0) s_stat[1] = rsqrtf(vv * (1.0f / DMODEL) + LN_EPS);
    }
    __syncthreads();
    float inv = s_stat[1];
    float y0 = d0 * inv * g[tid]       + bb[tid];
    float y1 = d1 * inv * g[tid + 256] + bb[tid + 256];
    h[base + tid]        = y0;
    h[base + tid + 256]  = y1;
    hr[base + tid]       = tf32r(y0);
    hr[base + tid + 256] = tf32r(y1);
}

/* ---------------- host driver ---------------- */
extern "C" void kernel_launch(void* const* d_in, const int* in_sizes, int n_in,
                              void* d_out, int out_size) {
    const int*   x    = (const int*)  d_in[0];
    const float* tok  = (const float*)d_in[1];
    const float* pos  = (const float*)d_in[2];
    const float* Wq   = (const float*)d_in[3];
    const float* Wk   = (const float*)d_in[4];
    const float* Wv   = (const float*)d_in[5];
    const float* Wo   = (const float*)d_in[6];
    const float* ln1g = (const float*)d_in[7];
    const float* ln1b = (const float*)d_in[8];
    const float* W1   = (const float*)d_in[9];
    const float* W2   = (const float*)d_in[10];
    const float* ln2g = (const float*)d_in[11];
    const float* ln2b = (const float*)d_in[12];
    const float* Wl   = (const float*)d_in[13];
    float* out = (float*)d_out;

    float *ph, *phr, *pq, *pk, *pv, *pa, *pt, *pff, *pw;
    cudaGetSymbolAddress((void**)&ph,  g_h);
    cudaGetSymbolAddress((void**)&phr, g_hr);
    cudaGetSymbolAddress((void**)&pq,  g_q);
    cudaGetSymbolAddress((void**)&pk,  g_k);
    cudaGetSymbolAddress((void**)&pv,  g_v);
    cudaGetSymbolAddress((void**)&pa,  g_a);
    cudaGetSymbolAddress((void**)&pt,  g_t);
    cudaGetSymbolAddress((void**)&pff, g_ff);
    cudaGetSymbolAddress((void**)&pw,  g_w);

    cudaFuncSetAttribute(attn_tc,    cudaFuncAttributeMaxDynamicSharedMemorySize, ATTN_SMEM);
    cudaFuncSetAttribute(gemm_tc<0>, cudaFuncAttributeMaxDynamicSharedMemorySize, G_SMEM);
    cudaFuncSetAttribute(gemm_tc<1>, cudaFuncAttributeMaxDynamicSharedMemorySize, G_SMEM);
    cudaFuncSetAttribute(gemm_qkv,   cudaFuncAttributeMaxDynamicSharedMemorySize, G_SMEM);

    prep_kernel<<<PB7 / 256, 256>>>(x, tok, pos,
        (const float4*)Wq, (const float4*)Wk, (const float4*)Wv, (const float4*)Wo,
        (const float4*)W1, (const float4*)W2, (const float4*)Wl,
        (float4*)pw, (float4*)ph, (float4*)phr);

    for (int i = 0; i < NDEPTH; i++) {
        const float* wq = pw + WOFF_Q + (size_t)i * DMODEL * DMODEL;
        const float* wk = pw + WOFF_K + (size_t)i * DMODEL * DMODEL;
        const float* wv = pw + WOFF_V + (size_t)i * DMODEL * DMODEL;
        const float* wo = pw + WOFF_O + (size_t)i * DMODEL * DMODEL;
        const float* w1 = pw + WOFF_1 + (size_t)i * DMODEL * DFFN;
        const float* w2 = pw + WOFF_2 + (size_t)i * DFFN * DMODEL;

        gemm_qkv<<<dim3(DMODEL / 128, MROWS / 128, 3), 256, G_SMEM>>>(
            phr, wq, wk, wv, pq, pk, pv, DMODEL, DMODEL);

        attn_tc<<<dim3(SEQ / 64, NHEADS, NB), 128, ATTN_SMEM>>>(pq, pk, pv, pa);

        gemm_tc<0><<<dim3(DMODEL / 128, MROWS / 128), 256, G_SMEM>>>(pa, wo, pt, DMODEL, DMODEL);
        ln_res_kernel<<<MROWS, 256>>>(ph, pt, ln1g + i * DMODEL, ln1b + i * DMODEL, phr);

        gemm_tc<1><<<dim3(DFFN / 128, MROWS / 128), 256, G_SMEM>>>(phr, w1, pff, DFFN, DMODEL);
        gemm_tc<0><<<dim3(DMODEL / 128, MROWS / 128), 256, G_SMEM>>>(pff, w2, pt, DMODEL, DFFN);
        ln_res_kernel<<<MROWS, 256>>>(ph, pt, ln2g + i * DMODEL, ln2b + i * DMODEL, phr);
    }

    gemm_tc<0><<<dim3(VOCAB / 128, MROWS / 128), 256, G_SMEM>>>(phr, pw + WOFF_L, out, VOCAB, DMODEL);
}